// round 14
// baseline (speedup 1.0000x reference)
#include <cuda_runtime.h>
#include <cuda_fp16.h>
#include <stdint.h>
#include <math.h>

#define NANCH 2304
#define NPROP 2000
#define NW1 36
#define NW2 32

// ---------------- scratch (device globals; no allocation) ----------------
__device__ float g_feat[64 * 256];
__device__ float g_featT[256 * 64];
__device__ float g_featP[64 * 18 * 18];
__device__ float g_hrpn[64 * 256];
__device__ float g_scores[NANCH];
__device__ float g_boxes[NANCH * 4];
__device__ int   g_order[NANCH];
__device__ float g_props[NPROP * 4];
__device__ int   g_valid[NPROP];
__device__ __half g_flath[NPROP * 3136];         // flat (pooled) split-fp16 hi
__device__ __half g_flatl[NPROP * 3136];         // flat split-fp16 lo
__device__ float g_h1[NPROP * 512];
__device__ float g_h2[NPROP * 512];
__device__ float g_rlogits[NPROP * 2];
__device__ float g_rdeltas[NPROP * 4];
__device__ float g_dscores[NPROP];
__device__ float g_s2[NPROP];
__device__ int   g_order2[NPROP];
__device__ float g_masks[NPROP * 196];
__device__ float g_dets[NPROP * 4];
__device__ unsigned short g_wh[9 * 64 * 64];     // mask-conv weights fp16 [slab][oc][ic]
__device__ float g_wpack[64 * 64 * 12];          // rpn-conv weights float4-aligned
__device__ __half g_flathz[3136];                // canonical zero-box flat hi/lo
__device__ __half g_flatlz[3136];
__device__ float g_maskz[196];
// split-fp16 FC weights, transposed [N][K]
__device__ __half g_bh1[512 * 3136];
__device__ __half g_bl1[512 * 3136];
__device__ __half g_bh2[512 * 512];
__device__ __half g_bl2[512 * 512];
// NMS scratch
__device__ float4 g_sb1[NANCH];
__device__ float  g_sa1[NANCH];
__device__ unsigned long long g_mask1[(size_t)NANCH * NW1];
__device__ int    g_keep1[NANCH];
__device__ float4 g_sb2[NPROP];
__device__ float  g_sa2[NPROP];
__device__ unsigned long long g_mask2[(size_t)NPROP * NW2];
__device__ int    g_keep2a[NPROP];

__device__ __forceinline__ void mma_f16(float* c, const unsigned* a,
                                        unsigned b0, unsigned b1) {
    asm volatile(
        "mma.sync.aligned.m16n8k16.row.col.f32.f16.f16.f32 "
        "{%0,%1,%2,%3},{%4,%5,%6,%7},{%8,%9},{%0,%1,%2,%3};"
        : "+f"(c[0]), "+f"(c[1]), "+f"(c[2]), "+f"(c[3])
        : "r"(a[0]), "r"(a[1]), "r"(a[2]), "r"(a[3]), "r"(b0), "r"(b1));
}

// ---------------- backbone ----------------
__global__ void k_backbone(const float* __restrict__ x, const float* __restrict__ w,
                           const float* __restrict__ b) {
    __shared__ float patch[768];
    __shared__ float part[256];
    int pos = blockIdx.x;
    int h = pos >> 4, wq = pos & 15;
    int tid = threadIdx.x;
    for (int k = tid; k < 768; k += 256) {
        int ic = k >> 8, r = k & 255, iy = r >> 4, ix = r & 15;
        patch[k] = x[ic * 65536 + (h * 16 + iy) * 256 + (wq * 16 + ix)];
    }
    __syncthreads();
    int oc = tid & 63, ch = tid >> 6;
    const float* wp = w + oc * 768 + ch * 192;
    const float* pp = patch + ch * 192;
    float a0 = 0.f, a1 = 0.f;
#pragma unroll 8
    for (int k = 0; k < 192; k += 2) { a0 += pp[k] * wp[k]; a1 += pp[k + 1] * wp[k + 1]; }
    part[tid] = a0 + a1;
    __syncthreads();
    if (tid < 64) {
        float s = b[tid] + part[tid] + part[tid + 64] + part[tid + 128] + part[tid + 192];
        float v = fmaxf(s, 0.f);
        g_feat[tid * 256 + pos] = v;
        g_featT[pos * 64 + tid] = v;
        g_featP[tid * 324 + (h + 1) * 18 + (wq + 1)] = v;
    }
}

// -------- pack rpn weights [oc][ic][9] -> [oc][ic][12] (float4-aligned) ----
__global__ void k_packw(const float* __restrict__ w) {
    int i = blockIdx.x * blockDim.x + threadIdx.x;
    if (i >= 64 * 64 * 12) return;
    int pair = i / 12, q = i % 12;
    g_wpack[i] = (q < 9) ? w[pair * 9 + q] : 0.f;
}

// ---------------- rpn conv 3x3 SAME, relu (8-way splitK, 512 thr) ----------------
__global__ void k_rpnconv(const float* __restrict__ b) {
    __shared__ float s_f[576];
    __shared__ float part[512];
    int pos = blockIdx.x;
    int y = pos >> 4, xq = pos & 15;
    int tid = threadIdx.x;     // 512
    for (int k = tid; k < 576; k += 512) {
        int ic = k / 9, r = k % 9, ky = r / 3, kx = r % 3;
        s_f[k] = g_featP[ic * 324 + (y + ky) * 18 + (xq + kx)];
    }
    __syncthreads();
    int oc = tid & 63, ch = tid >> 6;          // ch 0..7 -> 8 ic each
    const float4* wp4 = (const float4*)g_wpack;
    float acc0 = 0.f, acc1 = 0.f;
    for (int icl = 0; icl < 8; icl += 2) {
        int ic = ch * 8 + icl;
        float4 A0 = wp4[(oc * 64 + ic) * 3], A1 = wp4[(oc * 64 + ic) * 3 + 1],
               A2 = wp4[(oc * 64 + ic) * 3 + 2];
        float4 B0 = wp4[(oc * 64 + ic + 1) * 3], B1 = wp4[(oc * 64 + ic + 1) * 3 + 1],
               B2 = wp4[(oc * 64 + ic + 1) * 3 + 2];
        float wAr[9] = {A0.x, A0.y, A0.z, A0.w, A1.x, A1.y, A1.z, A1.w, A2.x};
        float wBr[9] = {B0.x, B0.y, B0.z, B0.w, B1.x, B1.y, B1.z, B1.w, B2.x};
        const float* f0 = s_f + ic * 9;
#pragma unroll
        for (int k = 0; k < 9; k++) {
            acc0 += f0[k] * wAr[k];
            acc1 += f0[9 + k] * wBr[k];
        }
    }
    part[tid] = acc0 + acc1;
    __syncthreads();
    if (tid < 64) {
        float s = b[tid];
#pragma unroll
        for (int j = 0; j < 8; j++) s += part[tid + 64 * j];
        g_hrpn[tid * 256 + pos] = fmaxf(s, 0.f);
    }
}

// -------- rpn heads (1x1), anchors, softmax score, decode, clip --------
__global__ void k_heads1(const float* __restrict__ wc, const float* __restrict__ bc,
                         const float* __restrict__ wb, const float* __restrict__ bb,
                         float* __restrict__ o_logits, float* __restrict__ o_deltas,
                         float* __restrict__ o_anch) {
    int i = blockIdx.x * blockDim.x + threadIdx.x;
    if (i >= NANCH) return;
    int cell = i / 9, a = i % 9;
    float l0 = bc[a * 2], l1 = bc[a * 2 + 1];
    float d0 = bb[a * 4], d1 = bb[a * 4 + 1], d2 = bb[a * 4 + 2], d3 = bb[a * 4 + 3];
    for (int ic = 0; ic < 64; ic++) {
        float f = g_hrpn[ic * 256 + cell];
        l0 += f * wc[(a * 2) * 64 + ic];
        l1 += f * wc[(a * 2 + 1) * 64 + ic];
        d0 += f * wb[(a * 4) * 64 + ic];
        d1 += f * wb[(a * 4 + 1) * 64 + ic];
        d2 += f * wb[(a * 4 + 2) * 64 + ic];
        d3 += f * wb[(a * 4 + 3) * 64 + ic];
    }
    o_logits[i * 2] = l0; o_logits[i * 2 + 1] = l1;
    o_deltas[i * 4] = d0; o_deltas[i * 4 + 1] = d1;
    o_deltas[i * 4 + 2] = d2; o_deltas[i * 4 + 3] = d3;
    float m = fmaxf(l0, l1);
    float e0 = expf(l0 - m), e1 = expf(l1 - m);
    g_scores[i] = e1 / (e0 + e1);

    const float S[3] = {32.f, 64.f, 128.f};
    const float R[3] = {0.5f, 1.f, 2.f};
    int h = cell >> 4, wq = cell & 15;
    float s = S[a / 3], r = R[a % 3];
    float ws = s * sqrtf(r), hs = s / sqrtf(r);
    float cx = (wq + 0.5f) * 16.f, cy = (h + 0.5f) * 16.f;
    float ax1 = cx - ws * 0.5f, ay1 = cy - hs * 0.5f;
    float ax2 = cx + ws * 0.5f, ay2 = cy + hs * 0.5f;
    o_anch[i * 4] = ax1; o_anch[i * 4 + 1] = ay1;
    o_anch[i * 4 + 2] = ax2; o_anch[i * 4 + 3] = ay2;

    float aw = ax2 - ax1, ah = ay2 - ay1;
    float acx = ax1 + 0.5f * aw, acy = ay1 + 0.5f * ah;
    float ncx = acx + d0 * aw, ncy = acy + d1 * ah;
    float nw = aw * expf(d2), nh = ah * expf(d3);
    g_boxes[i * 4]     = fminf(fmaxf(ncx - 0.5f * nw, 0.f), 255.f);
    g_boxes[i * 4 + 1] = fminf(fmaxf(ncy - 0.5f * nh, 0.f), 255.f);
    g_boxes[i * 4 + 2] = fminf(fmaxf(ncx + 0.5f * nw, 0.f), 255.f);
    g_boxes[i * 4 + 3] = fminf(fmaxf(ncy + 0.5f * nh, 0.f), 255.f);
}

// -------- pack mask-conv weights fp16 [slab][oc][ic] ----
__global__ void k_packwh(const float* __restrict__ w) {
    int i = blockIdx.x * blockDim.x + threadIdx.x;
    if (i >= 9 * 64 * 64) return;
    int slab = i >> 12, r = i & 4095, oc = r >> 6, ic = r & 63;
    g_wh[i] = __half_as_ushort(__float2half_rn(w[oc * 576 + ic * 9 + slab]));
}

// -------- tiled transpose pack: w[K][N] -> Bh/Bl [N][K] split-fp16 ----
__global__ void k_packBt(const float* __restrict__ w, __half* __restrict__ Bh,
                         __half* __restrict__ Bl, int K, int N) {
    __shared__ float tile[32][33];
    int kb = blockIdx.y * 32, nb = blockIdx.x * 32;
    int tx = threadIdx.x, ty = threadIdx.y;   // 32 x 8
#pragma unroll
    for (int i = 0; i < 32; i += 8) {
        int k = kb + ty + i, n = nb + tx;
        tile[ty + i][tx] = (k < K && n < N) ? w[(size_t)k * N + n] : 0.f;
    }
    __syncthreads();
#pragma unroll
    for (int i = 0; i < 32; i += 8) {
        int n = nb + ty + i, k = kb + tx;
        if (n < N && k < K) {
            float x = tile[tx][ty + i];
            __half h = __float2half_rn(x);
            Bh[(size_t)n * K + k] = h;
            Bl[(size_t)n * K + k] = __float2half_rn(x - __half2float(h));
        }
    }
}

// -------- single-block bitonic sort + fused box gather --------
template <int SIZE>
__global__ void k_sort(const float* __restrict__ sc, int n, int* __restrict__ ord,
                       const float* __restrict__ boxes, float4* __restrict__ sb,
                       float* __restrict__ sa) {
    __shared__ unsigned long long k[SIZE];
    int tid = threadIdx.x;
    for (int i = tid; i < SIZE; i += 1024) {
        if (i < n) {
            unsigned u = __float_as_uint(sc[i]);
            unsigned o = (u & 0x80000000u) ? ~u : (u | 0x80000000u);
            k[i] = ((unsigned long long)(~o) << 32) | (unsigned)i;
        } else k[i] = 0xFFFFFFFFFFFFFFFFULL;
    }
    __syncthreads();
    for (int kk = 2; kk <= SIZE; kk <<= 1) {
        for (int j = kk >> 1; j > 0; j >>= 1) {
            for (int i = tid; i < SIZE; i += 1024) {
                int ixj = i ^ j;
                if (ixj > i) {
                    bool up = ((i & kk) == 0);
                    unsigned long long a = k[i], b = k[ixj];
                    if ((a > b) == up) { k[i] = b; k[ixj] = a; }
                }
            }
            __syncthreads();
        }
    }
    for (int i = tid; i < n; i += 1024) {
        int idx = (int)(k[i] & 0xFFFFFFFFu);
        ord[i] = idx;
        float4 b = *(const float4*)&boxes[idx * 4];
        sb[i] = b;
        sa[i] = fmaxf(b.z - b.x, 0.f) * fmaxf(b.w - b.y, 0.f);
    }
}

// -------- IoU bitmask matrix --------
template <int N, int NW>
__global__ void k_ioumask(const float4* __restrict__ sb, const float* __restrict__ sa,
                          unsigned long long* __restrict__ mask, float thr) {
    __shared__ float4 cbx[64];
    __shared__ float car[64];
    int rb = blockIdx.y, cb = blockIdx.x;
    int t = threadIdx.x;
    int j0 = cb * 64;
    if (j0 + t < N) { cbx[t] = sb[j0 + t]; car[t] = sa[j0 + t]; }
    __syncthreads();
    int i = rb * 64 + t;
    if (i >= N) return;
    float4 bi = sb[i];
    float ai = sa[i];
    unsigned long long m = 0;
    int jmax = min(64, N - j0);
    for (int jj = 0; jj < jmax; jj++) {
        int j = j0 + jj;
        if (j <= i) continue;
        float xx1 = fmaxf(bi.x, cbx[jj].x), yy1 = fmaxf(bi.y, cbx[jj].y);
        float xx2 = fminf(bi.z, cbx[jj].z), yy2 = fminf(bi.w, cbx[jj].w);
        float inter = fmaxf(xx2 - xx1, 0.f) * fmaxf(yy2 - yy1, 0.f);
        float iou = inter / (ai + car[jj] - inter + 1e-8f);
        if (iou > thr) m |= 1ULL << jj;
    }
    mask[(size_t)i * NW + cb] = m;
}

// -------- chunked exact greedy reduce --------
template <int N, int NW>
__global__ void k_nmsreduce(const unsigned long long* __restrict__ mask,
                            int* __restrict__ keep) {
    __shared__ unsigned long long s_blk[64];
    int lane = threadIdx.x;
    unsigned long long remv0 = 0ULL, remv1 = 0ULL;
    const int NC = (N + 63) / 64;
    for (int cb = 0; cb < NC; cb++) {
        int j0 = cb * 64;
        int jmax = min(64, N - j0);
        for (int t = lane; t < jmax; t += 32)
            s_blk[t] = mask[(size_t)(j0 + t) * NW + cb];
        __syncwarp();
        int owner = cb & 31;
        unsigned long long r = __shfl_sync(0xffffffffu, (cb < 32) ? remv0 : remv1, owner);
        unsigned long long kept = 0ULL;
        if (lane == 0) {
#pragma unroll 4
            for (int jj = 0; jj < jmax; jj++) {
                if (!((r >> jj) & 1ULL)) {
                    kept |= 1ULL << jj;
                    r |= s_blk[jj];
                }
            }
        }
        kept = __shfl_sync(0xffffffffu, kept, 0);
        r = __shfl_sync(0xffffffffu, r, 0);
        if (lane == owner) { if (cb < 32) remv0 = r; else remv1 = r; }
        for (int t = lane; t < jmax; t += 32)
            keep[j0 + t] = (int)((kept >> t) & 1ULL);
        int w1 = lane, w2 = lane + 32;
        bool u1 = (w1 > cb) && (w1 < NW), u2 = (w2 > cb) && (w2 < NW);
        for (int jj = 0; jj < jmax; jj++) {
            if ((kept >> jj) & 1ULL) {
                const unsigned long long* row = mask + (size_t)(j0 + jj) * NW;
                if (u1) remv0 |= row[w1];
                if (u2) remv1 |= row[w2];
            }
        }
        __syncwarp();
    }
}

// -------- stable kept-first selection --------
__global__ void k_select1(float* __restrict__ o_props) {
    __shared__ int s_src[NPROP];
    int tid = threadIdx.x;
    if (tid < 32) {
        const int CH = NANCH / 32;
        int beg = tid * CH, end = beg + CH;
        int cnt = 0;
        for (int i = beg; i < end; i++) cnt += g_keep1[i];
        int xsc = cnt;
        for (int off = 1; off < 32; off <<= 1) {
            int v = __shfl_up_sync(0xffffffffu, xsc, off);
            if (tid >= off) xsc += v;
        }
        int excl = xsc - cnt;
        int total = __shfl_sync(0xffffffffu, xsc, 31);
        int kpos = excl;
        int npos = total + (beg - excl);
        for (int i = beg; i < end; i++) {
            int pos = g_keep1[i] ? kpos++ : npos++;
            if (pos < NPROP) s_src[pos] = i;
        }
    }
    __syncthreads();
    for (int p = tid; p < NPROP; p += 1024) {
        int i = s_src[p];
        int v = g_keep1[i];
        float4 bb = g_sb1[i];
        float px1 = v ? bb.x : 0.f, py1 = v ? bb.y : 0.f;
        float px2 = v ? bb.z : 0.f, py2 = v ? bb.w : 0.f;
        g_props[p * 4] = px1; g_props[p * 4 + 1] = py1;
        g_props[p * 4 + 2] = px2; g_props[p * 4 + 3] = py2;
        o_props[p * 4] = px1; o_props[p * 4 + 1] = py1;
        o_props[p * 4 + 2] = px2; o_props[p * 4 + 3] = py2;
        g_valid[p] = v;
    }
}

// ===================== ROI body: fp16 MMA implicit GEMM =====================
#define CROPH_H (16 * 16 * 72)
#define WSLAB_H (64 * 72)
#define SMEM_ROI_BYTES (CROPH_H * 2 + WSLAB_H * 2 + (64 + 64 + 28) * 4 + 56 * 4 + 16)

__device__ __forceinline__ void roi_body(
    int tid, float bx1, float by1, float bx2, float by2,
    const float* __restrict__ bm1, const float* __restrict__ wm2,
    const float* __restrict__ bm2,
    __half* __restrict__ flath, __half* __restrict__ flatl,
    float* __restrict__ maskA, float* __restrict__ maskB,
    __half* smem)
{
    __half* s_ch = smem;
    __half* s_wh = smem + CROPH_H;
    float* s_w2 = (float*)(smem + CROPH_H + WSLAB_H);
    float* s_b1 = s_w2 + 64;
    float* s_wy = s_b1 + 64;
    float* s_wx = s_wy + 14;
    int* s_y0 = (int*)(s_wx + 14);
    int* s_y1 = s_y0 + 14;
    int* s_x0 = s_y1 + 14;
    int* s_x1 = s_x0 + 14;

    int lane = tid & 31, wrp = tid >> 5;

    if (tid < 28) {
        int t = tid % 14;
        float tt = (float)t / 13.0f;
        if (tid < 14) {
            float y1n = by1 / 255.0f, y2n = by2 / 255.0f;
            float fy = (y1n + (y2n - y1n) * tt) * 15.0f;
            float y0f = fminf(fmaxf(floorf(fy), 0.f), 15.f);
            int y0 = (int)y0f;
            s_y0[t] = y0; s_y1[t] = min(y0 + 1, 15); s_wy[t] = fy - y0f;
        } else {
            float x1n = bx1 / 255.0f, x2n = bx2 / 255.0f;
            float fx = (x1n + (x2n - x1n) * tt) * 15.0f;
            float x0f = fminf(fmaxf(floorf(fx), 0.f), 15.f);
            int x0 = (int)x0f;
            s_x0[t] = x0; s_x1[t] = min(x0 + 1, 15); s_wx[t] = fx - x0f;
        }
    }
    if (tid >= 32 && tid < 96) {
        int c = tid - 32;
        s_w2[c] = wm2[c];
        s_b1[c] = bm1[c];
    }
    for (int idx = tid; idx < CROPH_H / 2; idx += 256)
        ((unsigned*)s_ch)[idx] = 0u;
    __syncthreads();

    const float4* ft4 = (const float4*)g_featT;
    for (int task = tid; task < 784; task += 256) {
        int cell = task >> 4, c4 = task & 15;
        int py = cell / 7, px = cell - py * 7;
        float4 v[2][2];
#pragma unroll
        for (int dy = 0; dy < 2; dy++)
#pragma unroll
            for (int dx = 0; dx < 2; dx++) {
                int ty = 2 * py + dy, tx = 2 * px + dx;
                int y0 = s_y0[ty], y1 = s_y1[ty], x0 = s_x0[tx], x1 = s_x1[tx];
                float wy = s_wy[ty], wx = s_wx[tx];
                float4 f00 = ft4[(y0 * 16 + x0) * 16 + c4];
                float4 f01 = ft4[(y0 * 16 + x1) * 16 + c4];
                float4 f10 = ft4[(y1 * 16 + x0) * 16 + c4];
                float4 f11 = ft4[(y1 * 16 + x1) * 16 + c4];
                float4 r;
                { float top = f00.x * (1.f - wx) + f01.x * wx;
                  float bot = f10.x * (1.f - wx) + f11.x * wx;
                  r.x = top * (1.f - wy) + bot * wy; }
                { float top = f00.y * (1.f - wx) + f01.y * wx;
                  float bot = f10.y * (1.f - wx) + f11.y * wx;
                  r.y = top * (1.f - wy) + bot * wy; }
                { float top = f00.z * (1.f - wx) + f01.z * wx;
                  float bot = f10.z * (1.f - wx) + f11.z * wx;
                  r.z = top * (1.f - wy) + bot * wy; }
                { float top = f00.w * (1.f - wx) + f01.w * wx;
                  float bot = f10.w * (1.f - wx) + f11.w * wx;
                  r.w = top * (1.f - wy) + bot * wy; }
                v[dy][dx] = r;
                __half2* dst = (__half2*)&s_ch[((ty + 1) * 16 + (tx + 1)) * 72 + c4 * 4];
                dst[0] = __floats2half2_rn(r.x, r.y);
                dst[1] = __floats2half2_rn(r.z, r.w);
            }
        // pool (exact fp32) then split to fp16 hi/lo for FC1
        float pv[4];
        pv[0] = fmaxf(fmaxf(v[0][0].x, v[0][1].x), fmaxf(v[1][0].x, v[1][1].x));
        pv[1] = fmaxf(fmaxf(v[0][0].y, v[0][1].y), fmaxf(v[1][0].y, v[1][1].y));
        pv[2] = fmaxf(fmaxf(v[0][0].z, v[0][1].z), fmaxf(v[1][0].z, v[1][1].z));
        pv[3] = fmaxf(fmaxf(v[0][0].w, v[0][1].w), fmaxf(v[1][0].w, v[1][1].w));
#pragma unroll
        for (int j = 0; j < 4; j++) {
            __half hh = __float2half_rn(pv[j]);
            int idx = (c4 * 4 + j) * 49 + cell;
            flath[idx] = hh;
            flatl[idx] = __float2half_rn(pv[j] - __half2float(hh));
        }
    }

    int g = lane >> 2, q = lane & 3;
    int pb[2][2];
#pragma unroll
    for (int mt = 0; mt < 2; mt++)
#pragma unroll
        for (int hh = 0; hh < 2; hh++) {
            int p = wrp * 32 + mt * 16 + g + hh * 8;
            if (p < 196) {
                int y = p / 14, xx = p % 14;
                pb[mt][hh] = (y * 16 + xx) * 72;
            } else pb[mt][hh] = 0;
        }

    float c[2][8][4];
#pragma unroll
    for (int mt = 0; mt < 2; mt++)
#pragma unroll
        for (int nt = 0; nt < 8; nt++)
#pragma unroll
            for (int j = 0; j < 4; j++) c[mt][nt][j] = 0.f;

    const unsigned* gwu = (const unsigned*)g_wh;
    for (int slab = 0; slab < 9; slab++) {
        __syncthreads();
        for (int f = tid; f < 2304; f += 256) {
            int oc = f / 36, icu = f - oc * 36;
            ((unsigned*)s_wh)[oc * 36 + icu] =
                (icu < 32) ? gwu[slab * 2048 + oc * 32 + icu] : 0u;
        }
        __syncthreads();
        int ky = slab / 3, kx = slab % 3;
        int off = (ky * 16 + kx) * 72;
#pragma unroll
        for (int kT = 0; kT < 4; kT++) {
            int ab = off + kT * 16 + 2 * q;
            unsigned a[2][4];
#pragma unroll
            for (int mt = 0; mt < 2; mt++) {
                a[mt][0] = *(const unsigned*)&s_ch[pb[mt][0] + ab];
                a[mt][1] = *(const unsigned*)&s_ch[pb[mt][1] + ab];
                a[mt][2] = *(const unsigned*)&s_ch[pb[mt][0] + ab + 8];
                a[mt][3] = *(const unsigned*)&s_ch[pb[mt][1] + ab + 8];
            }
            int bbase = kT * 16 + 2 * q;
#pragma unroll
            for (int nt = 0; nt < 8; nt++) {
                int oc = nt * 8 + g;
                unsigned b0 = *(const unsigned*)&s_wh[oc * 72 + bbase];
                unsigned b1 = *(const unsigned*)&s_wh[oc * 72 + bbase + 8];
                mma_f16(c[0][nt], a[0], b0, b1);
                mma_f16(c[1][nt], a[1], b0, b1);
            }
        }
    }

    float part[2][2] = {{0.f, 0.f}, {0.f, 0.f}};
#pragma unroll
    for (int nt = 0; nt < 8; nt++) {
        int col0 = nt * 8 + q * 2, col1 = col0 + 1;
        float bA = s_b1[col0], bB = s_b1[col1];
        float w20 = s_w2[col0], w21 = s_w2[col1];
#pragma unroll
        for (int mt = 0; mt < 2; mt++) {
            part[mt][0] += fmaxf(c[mt][nt][0] + bA, 0.f) * w20
                         + fmaxf(c[mt][nt][1] + bB, 0.f) * w21;
            part[mt][1] += fmaxf(c[mt][nt][2] + bA, 0.f) * w20
                         + fmaxf(c[mt][nt][3] + bB, 0.f) * w21;
        }
    }
    float b2 = bm2[0];
#pragma unroll
    for (int mt = 0; mt < 2; mt++)
#pragma unroll
        for (int hh = 0; hh < 2; hh++) {
            float v = part[mt][hh];
            v += __shfl_xor_sync(0xffffffffu, v, 1);
            v += __shfl_xor_sync(0xffffffffu, v, 2);
            int p = wrp * 32 + mt * 16 + g + hh * 8;
            if (q == 0 && p < 196) {
                float logit = b2 + v;
                maskA[p] = logit;
                maskB[p] = logit;
            }
        }
}

__global__ void __launch_bounds__(256, 2)
k_roizero(const float* __restrict__ bm1, const float* __restrict__ wm2,
          const float* __restrict__ bm2) {
    extern __shared__ __half smem_h[];
    roi_body(threadIdx.x, 0.f, 0.f, 0.f, 0.f, bm1, wm2, bm2,
             g_flathz, g_flatlz, g_maskz, g_maskz, smem_h);
}

__global__ void __launch_bounds__(256, 2)
k_roi(const float* __restrict__ bm1, const float* __restrict__ wm2,
      const float* __restrict__ bm2, float* __restrict__ omask) {
    extern __shared__ __half smem_h[];
    int p = blockIdx.x, tid = threadIdx.x;
    if (!g_valid[p]) {
        __half* fh = g_flath + (size_t)p * 3136;
        __half* fl = g_flatl + (size_t)p * 3136;
        // 3136 halves = 1568 unsigned words per plane
        for (int idx = tid; idx < 1568; idx += 256) {
            ((unsigned*)fh)[idx] = ((const unsigned*)g_flathz)[idx];
            ((unsigned*)fl)[idx] = ((const unsigned*)g_flatlz)[idx];
        }
        for (int pos = tid; pos < 196; pos += 256) {
            float v = g_maskz[pos];
            omask[(size_t)p * 196 + pos] = v;
            g_masks[(size_t)p * 196 + pos] = v;
        }
        return;
    }
    roi_body(tid, g_props[p * 4], g_props[p * 4 + 1], g_props[p * 4 + 2], g_props[p * 4 + 3],
             bm1, wm2, bm2,
             g_flath + (size_t)p * 3136, g_flatl + (size_t)p * 3136,
             omask + (size_t)p * 196, g_masks + (size_t)p * 196, smem_h);
}

// ===== split-fp16 GEMM (pre-split A), double-buffered: C = relu(A·B + bias) =====
__global__ void __launch_bounds__(256, 2)
k_gemmhp(const __half* __restrict__ Ah, const __half* __restrict__ Al,
         const __half* __restrict__ Bh, const __half* __restrict__ Bl,
         const float* __restrict__ bias, float* __restrict__ C,
         int M, int N, int K) {
    __shared__ __half sAh[2][64][40], sAl[2][64][40], sBh[2][64][40], sBl[2][64][40];
    int tid = threadIdx.x;
    int lane = tid & 31, wrp = tid >> 5;
    int wm = wrp >> 1, wn = wrp & 1;
    int g = lane >> 2, q = lane & 3;
    int bm = blockIdx.y * 64, bn = blockIdx.x * 64;

    float acc[4][4];
#pragma unroll
    for (int nt = 0; nt < 4; nt++)
#pragma unroll
        for (int j = 0; j < 4; j++) acc[nt][j] = 0.f;

    int lr = tid >> 2, lc = (tid & 3) * 8;
    int arow = bm + lr;
    bool aok = arow < M;
    const __half* ahrow = Ah + (size_t)(aok ? arow : 0) * K;
    const __half* alrow = Al + (size_t)(aok ? arow : 0) * K;
    const __half* bhrow = Bh + (size_t)(bn + lr) * K;
    const __half* blrow = Bl + (size_t)(bn + lr) * K;
    const int nk = K / 32;
    const uint4 z4 = make_uint4(0u, 0u, 0u, 0u);

    {
        *(uint4*)&sAh[0][lr][lc] = aok ? *(const uint4*)&ahrow[lc] : z4;
        *(uint4*)&sAl[0][lr][lc] = aok ? *(const uint4*)&alrow[lc] : z4;
        *(uint4*)&sBh[0][lr][lc] = *(const uint4*)&bhrow[lc];
        *(uint4*)&sBl[0][lr][lc] = *(const uint4*)&blrow[lc];
    }
    __syncthreads();

    for (int t = 0; t < nk; t++) {
        int cur = t & 1, nxt = cur ^ 1;
        uint4 wah, wal, wbh, wbl;
        bool havenext = (t + 1 < nk);
        if (havenext) {
            int k0 = (t + 1) * 32;
            wah = aok ? *(const uint4*)&ahrow[k0 + lc] : z4;
            wal = aok ? *(const uint4*)&alrow[k0 + lc] : z4;
            wbh = *(const uint4*)&bhrow[k0 + lc];
            wbl = *(const uint4*)&blrow[k0 + lc];
        }
#pragma unroll
        for (int kT = 0; kT < 2; kT++) {
            int kb = kT * 16 + 2 * q;
            int m0 = wm * 16 + g;
            unsigned ah[4], al[4];
            ah[0] = *(const unsigned*)&sAh[cur][m0][kb];
            ah[1] = *(const unsigned*)&sAh[cur][m0 + 8][kb];
            ah[2] = *(const unsigned*)&sAh[cur][m0][kb + 8];
            ah[3] = *(const unsigned*)&sAh[cur][m0 + 8][kb + 8];
            al[0] = *(const unsigned*)&sAl[cur][m0][kb];
            al[1] = *(const unsigned*)&sAl[cur][m0 + 8][kb];
            al[2] = *(const unsigned*)&sAl[cur][m0][kb + 8];
            al[3] = *(const unsigned*)&sAl[cur][m0 + 8][kb + 8];
#pragma unroll
            for (int nt = 0; nt < 4; nt++) {
                int n = wn * 32 + nt * 8 + g;
                unsigned bh0 = *(const unsigned*)&sBh[cur][n][kb];
                unsigned bh1 = *(const unsigned*)&sBh[cur][n][kb + 8];
                unsigned bl0 = *(const unsigned*)&sBl[cur][n][kb];
                unsigned bl1 = *(const unsigned*)&sBl[cur][n][kb + 8];
                mma_f16(acc[nt], ah, bh0, bh1);
                mma_f16(acc[nt], ah, bl0, bl1);
                mma_f16(acc[nt], al, bh0, bh1);
            }
        }
        if (havenext) {
            *(uint4*)&sAh[nxt][lr][lc] = wah;
            *(uint4*)&sAl[nxt][lr][lc] = wal;
            *(uint4*)&sBh[nxt][lr][lc] = wbh;
            *(uint4*)&sBl[nxt][lr][lc] = wbl;
        }
        __syncthreads();
    }
#pragma unroll
    for (int nt = 0; nt < 4; nt++) {
        int col0 = bn + wn * 32 + nt * 8 + 2 * q;
        float b0 = bias[col0], b1 = bias[col0 + 1];
        int r0 = bm + wm * 16 + g, r1 = r0 + 8;
        if (r0 < M) {
            C[(size_t)r0 * N + col0]     = fmaxf(acc[nt][0] + b0, 0.f);
            C[(size_t)r0 * N + col0 + 1] = fmaxf(acc[nt][1] + b1, 0.f);
        }
        if (r1 < M) {
            C[(size_t)r1 * N + col0]     = fmaxf(acc[nt][2] + b0, 0.f);
            C[(size_t)r1 * N + col0 + 1] = fmaxf(acc[nt][3] + b1, 0.f);
        }
    }
}

// ===== split-fp16 GEMM (fp32 A, on-the-fly split), double-buffered =====
__global__ void __launch_bounds__(256, 2)
k_gemmh(const float* __restrict__ A, const __half* __restrict__ Bh,
        const __half* __restrict__ Bl, const float* __restrict__ bias,
        float* __restrict__ C, int M, int N, int K) {
    __shared__ __half sAh[2][64][40], sAl[2][64][40], sBh[2][64][40], sBl[2][64][40];
    int tid = threadIdx.x;
    int lane = tid & 31, wrp = tid >> 5;
    int wm = wrp >> 1, wn = wrp & 1;
    int g = lane >> 2, q = lane & 3;
    int bm = blockIdx.y * 64, bn = blockIdx.x * 64;

    float acc[4][4];
#pragma unroll
    for (int nt = 0; nt < 4; nt++)
#pragma unroll
        for (int j = 0; j < 4; j++) acc[nt][j] = 0.f;

    int lr = tid >> 2, lc = (tid & 3) * 8;
    int arow = bm + lr;
    bool aok = arow < M;
    const __half* bhrow = Bh + (size_t)(bn + lr) * K;
    const __half* blrow = Bl + (size_t)(bn + lr) * K;
    const int nk = K / 32;

    {
        float4 v0 = make_float4(0.f, 0.f, 0.f, 0.f), v1 = v0;
        if (aok) {
            v0 = *(const float4*)&A[(size_t)arow * K + lc];
            v1 = *(const float4*)&A[(size_t)arow * K + lc + 4];
        }
        float vf[8] = {v0.x, v0.y, v0.z, v0.w, v1.x, v1.y, v1.z, v1.w};
#pragma unroll
        for (int j = 0; j < 8; j++) {
            __half h = __float2half_rn(vf[j]);
            sAh[0][lr][lc + j] = h;
            sAl[0][lr][lc + j] = __float2half_rn(vf[j] - __half2float(h));
        }
        *(uint4*)&sBh[0][lr][lc] = *(const uint4*)&bhrow[lc];
        *(uint4*)&sBl[0][lr][lc] = *(const uint4*)&blrow[lc];
    }
    __syncthreads();

    for (int t = 0; t < nk; t++) {
        int cur = t & 1, nxt = cur ^ 1;
        float4 v0, v1;
        uint4 wbh, wbl;
        bool havenext = (t + 1 < nk);
        if (havenext) {
            int k0 = (t + 1) * 32;
            v0 = make_float4(0.f, 0.f, 0.f, 0.f); v1 = v0;
            if (aok) {
                v0 = *(const float4*)&A[(size_t)arow * K + k0 + lc];
                v1 = *(const float4*)&A[(size_t)arow * K + k0 + lc + 4];
            }
            wbh = *(const uint4*)&bhrow[k0 + lc];
            wbl = *(const uint4*)&blrow[k0 + lc];
        }
#pragma unroll
        for (int kT = 0; kT < 2; kT++) {
            int kb = kT * 16 + 2 * q;
            int m0 = wm * 16 + g;
            unsigned ah[4], al[4];
            ah[0] = *(const unsigned*)&sAh[cur][m0][kb];
            ah[1] = *(const unsigned*)&sAh[cur][m0 + 8][kb];
            ah[2] = *(const unsigned*)&sAh[cur][m0][kb + 8];
            ah[3] = *(const unsigned*)&sAh[cur][m0 + 8][kb + 8];
            al[0] = *(const unsigned*)&sAl[cur][m0][kb];
            al[1] = *(const unsigned*)&sAl[cur][m0 + 8][kb];
            al[2] = *(const unsigned*)&sAl[cur][m0][kb + 8];
            al[3] = *(const unsigned*)&sAl[cur][m0 + 8][kb + 8];
#pragma unroll
            for (int nt = 0; nt < 4; nt++) {
                int n = wn * 32 + nt * 8 + g;
                unsigned bh0 = *(const unsigned*)&sBh[cur][n][kb];
                unsigned bh1 = *(const unsigned*)&sBh[cur][n][kb + 8];
                unsigned bl0 = *(const unsigned*)&sBl[cur][n][kb];
                unsigned bl1 = *(const unsigned*)&sBl[cur][n][kb + 8];
                mma_f16(acc[nt], ah, bh0, bh1);
                mma_f16(acc[nt], ah, bl0, bl1);
                mma_f16(acc[nt], al, bh0, bh1);
            }
        }
        if (havenext) {
            float vf[8] = {v0.x, v0.y, v0.z, v0.w, v1.x, v1.y, v1.z, v1.w};
#pragma unroll
            for (int j = 0; j < 8; j++) {
                __half h = __float2half_rn(vf[j]);
                sAh[nxt][lr][lc + j] = h;
                sAl[nxt][lr][lc + j] = __float2half_rn(vf[j] - __half2float(h));
            }
            *(uint4*)&sBh[nxt][lr][lc] = wbh;
            *(uint4*)&sBl[nxt][lr][lc] = wbl;
        }
        __syncthreads();
    }
#pragma unroll
    for (int nt = 0; nt < 4; nt++) {
        int col0 = bn + wn * 32 + nt * 8 + 2 * q;
        float b0 = bias[col0], b1 = bias[col0 + 1];
        int r0 = bm + wm * 16 + g, r1 = r0 + 8;
        if (r0 < M) {
            C[(size_t)r0 * N + col0]     = fmaxf(acc[nt][0] + b0, 0.f);
            C[(size_t)r0 * N + col0 + 1] = fmaxf(acc[nt][1] + b1, 0.f);
        }
        if (r1 < M) {
            C[(size_t)r1 * N + col0]     = fmaxf(acc[nt][2] + b0, 0.f);
            C[(size_t)r1 * N + col0 + 1] = fmaxf(acc[nt][3] + b1, 0.f);
        }
    }
}

// -------- rcnn cls/box heads + fused stage-2 decode --------
__global__ void k_rheads(const float* __restrict__ wrc, const float* __restrict__ brc,
                         const float* __restrict__ wrb, const float* __restrict__ brb,
                         float* __restrict__ o_log, float* __restrict__ o_del,
                         float* __restrict__ dets) {
    __shared__ float s6[6];
    int p = blockIdx.x;
    int w = threadIdx.x >> 5, lane = threadIdx.x & 31;
    const float* hp = g_h2 + (size_t)p * 512;
    float s = 0.f;
    if (w < 2) {
        for (int k = lane; k < 512; k += 32) s += hp[k] * wrc[k * 2 + w];
    } else {
        int j = w - 2;
        for (int k = lane; k < 512; k += 32) s += hp[k] * wrb[k * 4 + j];
    }
    for (int off = 16; off > 0; off >>= 1) s += __shfl_down_sync(0xffffffffu, s, off);
    if (lane == 0) {
        if (w < 2) {
            float v = s + brc[w];
            o_log[p * 2 + w] = v;
            g_rlogits[p * 2 + w] = v;
            s6[w] = v;
        } else {
            int j = w - 2;
            float v = s + brb[j];
            o_del[p * 4 + j] = v;
            g_rdeltas[p * 4 + j] = v;
            s6[w] = v;
        }
    }
    __syncthreads();
    if (threadIdx.x == 0) {
        float l0 = s6[0], l1 = s6[1];
        float m = fmaxf(l0, l1);
        float e0 = expf(l0 - m), e1 = expf(l1 - m);
        float sc = e1 / (e0 + e1);
        g_dscores[p] = sc;
        float x1 = g_props[p * 4], y1 = g_props[p * 4 + 1];
        float x2 = g_props[p * 4 + 2], y2 = g_props[p * 4 + 3];
        float wd = x2 - x1, h = y2 - y1;
        float cx = x1 + 0.5f * wd, cy = y1 + 0.5f * h;
        float d0 = s6[2], d1 = s6[3], d2 = s6[4], d3 = s6[5];
        float ncx = cx + d0 * wd, ncy = cy + d1 * h;
        float nw = wd * expf(d2), nh = h * expf(d3);
        dets[p * 4]     = fminf(fmaxf(ncx - 0.5f * nw, 0.f), 255.f);
        dets[p * 4 + 1] = fminf(fmaxf(ncy - 0.5f * nh, 0.f), 255.f);
        dets[p * 4 + 2] = fminf(fmaxf(ncx + 0.5f * nw, 0.f), 255.f);
        dets[p * 4 + 3] = fminf(fmaxf(ncy + 0.5f * nh, 0.f), 255.f);
        g_s2[p] = g_valid[p] ? sc : -1.0f;
    }
}

// -------- final dets/scores/keep2 + masks (fused) --------
__global__ void k_final(float* __restrict__ o_fdets, float* __restrict__ o_fsc,
                        float* __restrict__ o_keep, float* __restrict__ o_fmsk) {
    __shared__ float s_kf;
    __shared__ int s_oi;
    int r = blockIdx.x, i = threadIdx.x;
    if (i == 0) {
        int o = g_order2[r];
        int k2 = g_keep2a[r] && g_valid[o];
        float kf = k2 ? 1.f : 0.f;
        float4 d = g_sb2[r];
        o_fdets[r * 4]     = k2 ? d.x : 0.f;
        o_fdets[r * 4 + 1] = k2 ? d.y : 0.f;
        o_fdets[r * 4 + 2] = k2 ? d.z : 0.f;
        o_fdets[r * 4 + 3] = k2 ? d.w : 0.f;
        o_fsc[r] = k2 ? g_dscores[o] : 0.f;
        if (o_keep) o_keep[r] = kf;
        s_kf = kf;
        s_oi = o;
    }
    __syncthreads();
    float v = g_masks[(size_t)s_oi * 196 + i];
    float sgm = 1.f / (1.f + expf(-v));
    o_fmsk[(size_t)r * 196 + i] = sgm * s_kf;
}

// ---------------- host ----------------
extern "C" void kernel_launch(void* const* d_in, const int* in_sizes, int n_in,
                              void* d_out, int out_size) {
    const float* x      = (const float*)d_in[0];
    const float* w_bb   = (const float*)d_in[1];
    const float* b_bb   = (const float*)d_in[2];
    const float* w_rpn  = (const float*)d_in[3];
    const float* b_rpn  = (const float*)d_in[4];
    const float* w_cls  = (const float*)d_in[5];
    const float* b_cls  = (const float*)d_in[6];
    const float* w_box  = (const float*)d_in[7];
    const float* b_box  = (const float*)d_in[8];
    const float* w_fc1  = (const float*)d_in[9];
    const float* b_fc1  = (const float*)d_in[10];
    const float* w_fc2  = (const float*)d_in[11];
    const float* b_fc2  = (const float*)d_in[12];
    const float* w_rcls = (const float*)d_in[13];
    const float* b_rcls = (const float*)d_in[14];
    const float* w_rbox = (const float*)d_in[15];
    const float* b_rbox = (const float*)d_in[16];
    const float* w_m1   = (const float*)d_in[17];
    const float* b_m1   = (const float*)d_in[18];
    const float* w_m2   = (const float*)d_in[19];
    const float* b_m2   = (const float*)d_in[20];
    float* out = (float*)d_out;

    const size_t O_RPNL = 0, O_RPND = 4608, O_PROP = 13824, O_ANCH = 21824;
    const size_t O_RLOG = 31040, O_RDEL = 35040, O_RMSK = 43040;
    const size_t O_FDET = 435040, O_FMSK = 443040, O_FSC = 835040, O_KEEP = 837040;

    float *p_scores, *p_s2, *p_h1, *p_h2, *p_dets, *p_boxes;
    int *p_order, *p_order2, *p_keep1, *p_keep2a;
    unsigned long long *p_mask1, *p_mask2;
    __half *p_bh1, *p_bl1, *p_bh2, *p_bl2, *p_fh, *p_fl;
    cudaGetSymbolAddress((void**)&p_scores, g_scores);
    cudaGetSymbolAddress((void**)&p_order, g_order);
    cudaGetSymbolAddress((void**)&p_s2, g_s2);
    cudaGetSymbolAddress((void**)&p_order2, g_order2);
    cudaGetSymbolAddress((void**)&p_h1, g_h1);
    cudaGetSymbolAddress((void**)&p_h2, g_h2);
    cudaGetSymbolAddress((void**)&p_dets, g_dets);
    cudaGetSymbolAddress((void**)&p_boxes, g_boxes);
    cudaGetSymbolAddress((void**)&p_keep1, g_keep1);
    cudaGetSymbolAddress((void**)&p_keep2a, g_keep2a);
    cudaGetSymbolAddress((void**)&p_mask1, g_mask1);
    cudaGetSymbolAddress((void**)&p_mask2, g_mask2);
    cudaGetSymbolAddress((void**)&p_bh1, g_bh1);
    cudaGetSymbolAddress((void**)&p_bl1, g_bl1);
    cudaGetSymbolAddress((void**)&p_bh2, g_bh2);
    cudaGetSymbolAddress((void**)&p_bl2, g_bl2);
    cudaGetSymbolAddress((void**)&p_fh, g_flath);
    cudaGetSymbolAddress((void**)&p_fl, g_flatl);

    cudaFuncSetAttribute(k_roi, cudaFuncAttributeMaxDynamicSharedMemorySize, SMEM_ROI_BYTES);
    cudaFuncSetAttribute(k_roizero, cudaFuncAttributeMaxDynamicSharedMemorySize, SMEM_ROI_BYTES);

    float4* p_sb1; float* p_sa1; float4* p_sb2; float* p_sa2;
    cudaGetSymbolAddress((void**)&p_sb1, g_sb1);
    cudaGetSymbolAddress((void**)&p_sa1, g_sa1);
    cudaGetSymbolAddress((void**)&p_sb2, g_sb2);
    cudaGetSymbolAddress((void**)&p_sa2, g_sa2);

    k_backbone<<<256, 256>>>(x, w_bb, b_bb);
    k_packwh<<<(9 * 64 * 64 + 255) / 256, 256>>>(w_m1);
    k_packw<<<(64 * 64 * 12 + 255) / 256, 256>>>(w_rpn);
    {
        dim3 tb(32, 8);
        k_packBt<<<dim3(512 / 32, 3136 / 32), tb>>>(w_fc1, p_bh1, p_bl1, 3136, 512);
        k_packBt<<<dim3(512 / 32, 512 / 32), tb>>>(w_fc2, p_bh2, p_bl2, 512, 512);
    }
    k_roizero<<<1, 256, SMEM_ROI_BYTES>>>(b_m1, w_m2, b_m2);
    k_rpnconv<<<256, 512>>>(b_rpn);
    k_heads1<<<18, 128>>>(w_cls, b_cls, w_box, b_box,
                          out + O_RPNL, out + O_RPND, out + O_ANCH);
    k_sort<4096><<<1, 1024>>>(p_scores, NANCH, p_order, p_boxes, p_sb1, p_sa1);
    k_ioumask<NANCH, NW1><<<dim3(NW1, NW1), 64>>>(p_sb1, p_sa1, p_mask1, 0.5f);
    k_nmsreduce<NANCH, NW1><<<1, 32>>>(p_mask1, p_keep1);
    k_select1<<<1, 1024>>>(out + O_PROP);
    k_roi<<<NPROP, 256, SMEM_ROI_BYTES>>>(b_m1, w_m2, b_m2, out + O_RMSK);

    dim3 gfc(8, 32);
    k_gemmhp<<<gfc, 256>>>(p_fh, p_fl, p_bh1, p_bl1, b_fc1, p_h1, NPROP, 512, 3136);
    k_gemmh<<<gfc, 256>>>(p_h1, p_bh2, p_bl2, b_fc2, p_h2, NPROP, 512, 512);
    k_rheads<<<NPROP, 192>>>(w_rcls, b_rcls, w_rbox, b_rbox,
                             out + O_RLOG, out + O_RDEL, p_dets);
    k_sort<2048><<<1, 1024>>>(p_s2, NPROP, p_order2, p_dets, p_sb2, p_sa2);
    k_ioumask<NPROP, NW2><<<dim3(NW2, NW2), 64>>>(p_sb2, p_sa2, p_mask2, 0.3f);
    k_nmsreduce<NPROP, NW2><<<1, 32>>>(p_mask2, p_keep2a);
    float* o_keep = (out_size >= (int)(O_KEEP + NPROP)) ? (out + O_KEEP) : nullptr;
    k_final<<<NPROP, 196>>>(out + O_FDET, out + O_FSC, o_keep, out + O_FMSK);
}

// round 15
// speedup vs baseline: 1.4542x; 1.4542x over previous
#include <cuda_runtime.h>
#include <cuda_fp16.h>
#include <stdint.h>
#include <math.h>

#define NANCH 2304
#define NPROP 2000
#define NW1 36
#define NW2 32

// ---------------- scratch (device globals; no allocation) ----------------
__device__ float g_feat[64 * 256];
__device__ float g_featT[256 * 64];
__device__ float g_featP[64 * 18 * 18];
__device__ float g_hrpn[64 * 256];
__device__ float g_scores[NANCH];
__device__ float g_boxes[NANCH * 4];
__device__ int   g_order[NANCH];
__device__ float g_props[NPROP * 4];
__device__ int   g_valid[NPROP];
__device__ float g_flat[NPROP * 3136];
__device__ float g_h1[NPROP * 512];
__device__ float g_h2[NPROP * 512];
__device__ float g_rlogits[NPROP * 2];
__device__ float g_rdeltas[NPROP * 4];
__device__ float g_dscores[NPROP];
__device__ float g_s2[NPROP];
__device__ int   g_order2[NPROP];
__device__ float g_masks[NPROP * 196];
__device__ float g_dets[NPROP * 4];
__device__ unsigned short g_wh[9 * 64 * 64];     // mask-conv weights fp16 [slab][oc][ic]
__device__ float g_wpack[64 * 64 * 12];          // rpn-conv weights float4-aligned
__device__ float g_flatz[3136];
__device__ float g_maskz[196];
// split-fp16 FC weights, transposed [N][K]
__device__ __half g_bh1[512 * 3136];
__device__ __half g_bl1[512 * 3136];
__device__ __half g_bh2[512 * 512];
__device__ __half g_bl2[512 * 512];
// NMS scratch
__device__ float4 g_sb1[NANCH];
__device__ float  g_sa1[NANCH];
__device__ unsigned long long g_mask1[(size_t)NANCH * NW1];
__device__ int    g_keep1[NANCH];
__device__ float4 g_sb2[NPROP];
__device__ float  g_sa2[NPROP];
__device__ unsigned long long g_mask2[(size_t)NPROP * NW2];
__device__ int    g_keep2a[NPROP];

__device__ __forceinline__ void mma_f16(float* c, const unsigned* a,
                                        unsigned b0, unsigned b1) {
    asm volatile(
        "mma.sync.aligned.m16n8k16.row.col.f32.f16.f16.f32 "
        "{%0,%1,%2,%3},{%4,%5,%6,%7},{%8,%9},{%0,%1,%2,%3};"
        : "+f"(c[0]), "+f"(c[1]), "+f"(c[2]), "+f"(c[3])
        : "r"(a[0]), "r"(a[1]), "r"(a[2]), "r"(a[3]), "r"(b0), "r"(b1));
}

// ---------------- backbone ----------------
__global__ void k_backbone(const float* __restrict__ x, const float* __restrict__ w,
                           const float* __restrict__ b) {
    __shared__ float patch[768];
    __shared__ float part[256];
    int pos = blockIdx.x;
    int h = pos >> 4, wq = pos & 15;
    int tid = threadIdx.x;
    for (int k = tid; k < 768; k += 256) {
        int ic = k >> 8, r = k & 255, iy = r >> 4, ix = r & 15;
        patch[k] = x[ic * 65536 + (h * 16 + iy) * 256 + (wq * 16 + ix)];
    }
    __syncthreads();
    int oc = tid & 63, ch = tid >> 6;
    const float* wp = w + oc * 768 + ch * 192;
    const float* pp = patch + ch * 192;
    float a0 = 0.f, a1 = 0.f;
#pragma unroll 8
    for (int k = 0; k < 192; k += 2) { a0 += pp[k] * wp[k]; a1 += pp[k + 1] * wp[k + 1]; }
    part[tid] = a0 + a1;
    __syncthreads();
    if (tid < 64) {
        float s = b[tid] + part[tid] + part[tid + 64] + part[tid + 128] + part[tid + 192];
        float v = fmaxf(s, 0.f);
        g_feat[tid * 256 + pos] = v;
        g_featT[pos * 64 + tid] = v;
        g_featP[tid * 324 + (h + 1) * 18 + (wq + 1)] = v;
    }
}

// -------- pack rpn weights [oc][ic][9] -> [oc][ic][12] (float4-aligned) ----
__global__ void k_packw(const float* __restrict__ w) {
    int i = blockIdx.x * blockDim.x + threadIdx.x;
    if (i >= 64 * 64 * 12) return;
    int pair = i / 12, q = i % 12;
    g_wpack[i] = (q < 9) ? w[pair * 9 + q] : 0.f;
}

// ---------------- rpn conv 3x3 SAME, relu (8-way splitK, 512 thr) ----------------
__global__ void k_rpnconv(const float* __restrict__ b) {
    __shared__ float s_f[576];
    __shared__ float part[512];
    int pos = blockIdx.x;
    int y = pos >> 4, xq = pos & 15;
    int tid = threadIdx.x;     // 512
    for (int k = tid; k < 576; k += 512) {
        int ic = k / 9, r = k % 9, ky = r / 3, kx = r % 3;
        s_f[k] = g_featP[ic * 324 + (y + ky) * 18 + (xq + kx)];
    }
    __syncthreads();
    int oc = tid & 63, ch = tid >> 6;
    const float4* wp4 = (const float4*)g_wpack;
    float acc0 = 0.f, acc1 = 0.f;
    for (int icl = 0; icl < 8; icl += 2) {
        int ic = ch * 8 + icl;
        float4 A0 = wp4[(oc * 64 + ic) * 3], A1 = wp4[(oc * 64 + ic) * 3 + 1],
               A2 = wp4[(oc * 64 + ic) * 3 + 2];
        float4 B0 = wp4[(oc * 64 + ic + 1) * 3], B1 = wp4[(oc * 64 + ic + 1) * 3 + 1],
               B2 = wp4[(oc * 64 + ic + 1) * 3 + 2];
        float wAr[9] = {A0.x, A0.y, A0.z, A0.w, A1.x, A1.y, A1.z, A1.w, A2.x};
        float wBr[9] = {B0.x, B0.y, B0.z, B0.w, B1.x, B1.y, B1.z, B1.w, B2.x};
        const float* f0 = s_f + ic * 9;
#pragma unroll
        for (int k = 0; k < 9; k++) {
            acc0 += f0[k] * wAr[k];
            acc1 += f0[9 + k] * wBr[k];
        }
    }
    part[tid] = acc0 + acc1;
    __syncthreads();
    if (tid < 64) {
        float s = b[tid];
#pragma unroll
        for (int j = 0; j < 8; j++) s += part[tid + 64 * j];
        g_hrpn[tid * 256 + pos] = fmaxf(s, 0.f);
    }
}

// -------- rpn heads (1x1), anchors, softmax score, decode, clip --------
__global__ void k_heads1(const float* __restrict__ wc, const float* __restrict__ bc,
                         const float* __restrict__ wb, const float* __restrict__ bb,
                         float* __restrict__ o_logits, float* __restrict__ o_deltas,
                         float* __restrict__ o_anch) {
    int i = blockIdx.x * blockDim.x + threadIdx.x;
    if (i >= NANCH) return;
    int cell = i / 9, a = i % 9;
    float l0 = bc[a * 2], l1 = bc[a * 2 + 1];
    float d0 = bb[a * 4], d1 = bb[a * 4 + 1], d2 = bb[a * 4 + 2], d3 = bb[a * 4 + 3];
    for (int ic = 0; ic < 64; ic++) {
        float f = g_hrpn[ic * 256 + cell];
        l0 += f * wc[(a * 2) * 64 + ic];
        l1 += f * wc[(a * 2 + 1) * 64 + ic];
        d0 += f * wb[(a * 4) * 64 + ic];
        d1 += f * wb[(a * 4 + 1) * 64 + ic];
        d2 += f * wb[(a * 4 + 2) * 64 + ic];
        d3 += f * wb[(a * 4 + 3) * 64 + ic];
    }
    o_logits[i * 2] = l0; o_logits[i * 2 + 1] = l1;
    o_deltas[i * 4] = d0; o_deltas[i * 4 + 1] = d1;
    o_deltas[i * 4 + 2] = d2; o_deltas[i * 4 + 3] = d3;
    float m = fmaxf(l0, l1);
    float e0 = expf(l0 - m), e1 = expf(l1 - m);
    g_scores[i] = e1 / (e0 + e1);

    const float S[3] = {32.f, 64.f, 128.f};
    const float R[3] = {0.5f, 1.f, 2.f};
    int h = cell >> 4, wq = cell & 15;
    float s = S[a / 3], r = R[a % 3];
    float ws = s * sqrtf(r), hs = s / sqrtf(r);
    float cx = (wq + 0.5f) * 16.f, cy = (h + 0.5f) * 16.f;
    float ax1 = cx - ws * 0.5f, ay1 = cy - hs * 0.5f;
    float ax2 = cx + ws * 0.5f, ay2 = cy + hs * 0.5f;
    o_anch[i * 4] = ax1; o_anch[i * 4 + 1] = ay1;
    o_anch[i * 4 + 2] = ax2; o_anch[i * 4 + 3] = ay2;

    float aw = ax2 - ax1, ah = ay2 - ay1;
    float acx = ax1 + 0.5f * aw, acy = ay1 + 0.5f * ah;
    float ncx = acx + d0 * aw, ncy = acy + d1 * ah;
    float nw = aw * expf(d2), nh = ah * expf(d3);
    g_boxes[i * 4]     = fminf(fmaxf(ncx - 0.5f * nw, 0.f), 255.f);
    g_boxes[i * 4 + 1] = fminf(fmaxf(ncy - 0.5f * nh, 0.f), 255.f);
    g_boxes[i * 4 + 2] = fminf(fmaxf(ncx + 0.5f * nw, 0.f), 255.f);
    g_boxes[i * 4 + 3] = fminf(fmaxf(ncy + 0.5f * nh, 0.f), 255.f);
}

// -------- pack mask-conv weights fp16 [slab][oc][ic] ----
__global__ void k_packwh(const float* __restrict__ w) {
    int i = blockIdx.x * blockDim.x + threadIdx.x;
    if (i >= 9 * 64 * 64) return;
    int slab = i >> 12, r = i & 4095, oc = r >> 6, ic = r & 63;
    g_wh[i] = __half_as_ushort(__float2half_rn(w[oc * 576 + ic * 9 + slab]));
}

// -------- tiled transpose pack: w[K][N] -> Bh/Bl [N][K] split-fp16 ----
__global__ void k_packBt(const float* __restrict__ w, __half* __restrict__ Bh,
                         __half* __restrict__ Bl, int K, int N) {
    __shared__ float tile[32][33];
    int kb = blockIdx.y * 32, nb = blockIdx.x * 32;
    int tx = threadIdx.x, ty = threadIdx.y;   // 32 x 8
#pragma unroll
    for (int i = 0; i < 32; i += 8) {
        int k = kb + ty + i, n = nb + tx;
        tile[ty + i][tx] = (k < K && n < N) ? w[(size_t)k * N + n] : 0.f;
    }
    __syncthreads();
#pragma unroll
    for (int i = 0; i < 32; i += 8) {
        int n = nb + ty + i, k = kb + tx;
        if (n < N && k < K) {
            float x = tile[tx][ty + i];
            __half h = __float2half_rn(x);
            Bh[(size_t)n * K + k] = h;
            Bl[(size_t)n * K + k] = __float2half_rn(x - __half2float(h));
        }
    }
}

// -------- single-block bitonic sort + fused box gather --------
template <int SIZE>
__global__ void k_sort(const float* __restrict__ sc, int n, int* __restrict__ ord,
                       const float* __restrict__ boxes, float4* __restrict__ sb,
                       float* __restrict__ sa) {
    __shared__ unsigned long long k[SIZE];
    int tid = threadIdx.x;
    for (int i = tid; i < SIZE; i += 1024) {
        if (i < n) {
            unsigned u = __float_as_uint(sc[i]);
            unsigned o = (u & 0x80000000u) ? ~u : (u | 0x80000000u);
            k[i] = ((unsigned long long)(~o) << 32) | (unsigned)i;
        } else k[i] = 0xFFFFFFFFFFFFFFFFULL;
    }
    __syncthreads();
    for (int kk = 2; kk <= SIZE; kk <<= 1) {
        for (int j = kk >> 1; j > 0; j >>= 1) {
            for (int i = tid; i < SIZE; i += 1024) {
                int ixj = i ^ j;
                if (ixj > i) {
                    bool up = ((i & kk) == 0);
                    unsigned long long a = k[i], b = k[ixj];
                    if ((a > b) == up) { k[i] = b; k[ixj] = a; }
                }
            }
            __syncthreads();
        }
    }
    for (int i = tid; i < n; i += 1024) {
        int idx = (int)(k[i] & 0xFFFFFFFFu);
        ord[i] = idx;
        float4 b = *(const float4*)&boxes[idx * 4];
        sb[i] = b;
        sa[i] = fmaxf(b.z - b.x, 0.f) * fmaxf(b.w - b.y, 0.f);
    }
}

// -------- IoU bitmask matrix --------
template <int N, int NW>
__global__ void k_ioumask(const float4* __restrict__ sb, const float* __restrict__ sa,
                          unsigned long long* __restrict__ mask, float thr) {
    __shared__ float4 cbx[64];
    __shared__ float car[64];
    int rb = blockIdx.y, cb = blockIdx.x;
    int t = threadIdx.x;
    int j0 = cb * 64;
    if (j0 + t < N) { cbx[t] = sb[j0 + t]; car[t] = sa[j0 + t]; }
    __syncthreads();
    int i = rb * 64 + t;
    if (i >= N) return;
    float4 bi = sb[i];
    float ai = sa[i];
    unsigned long long m = 0;
    int jmax = min(64, N - j0);
    for (int jj = 0; jj < jmax; jj++) {
        int j = j0 + jj;
        if (j <= i) continue;
        float xx1 = fmaxf(bi.x, cbx[jj].x), yy1 = fmaxf(bi.y, cbx[jj].y);
        float xx2 = fminf(bi.z, cbx[jj].z), yy2 = fminf(bi.w, cbx[jj].w);
        float inter = fmaxf(xx2 - xx1, 0.f) * fmaxf(yy2 - yy1, 0.f);
        float iou = inter / (ai + car[jj] - inter + 1e-8f);
        if (iou > thr) m |= 1ULL << jj;
    }
    mask[(size_t)i * NW + cb] = m;
}

// -------- chunked exact greedy reduce --------
template <int N, int NW>
__global__ void k_nmsreduce(const unsigned long long* __restrict__ mask,
                            int* __restrict__ keep) {
    __shared__ unsigned long long s_blk[64];
    int lane = threadIdx.x;
    unsigned long long remv0 = 0ULL, remv1 = 0ULL;
    const int NC = (N + 63) / 64;
    for (int cb = 0; cb < NC; cb++) {
        int j0 = cb * 64;
        int jmax = min(64, N - j0);
        for (int t = lane; t < jmax; t += 32)
            s_blk[t] = mask[(size_t)(j0 + t) * NW + cb];
        __syncwarp();
        int owner = cb & 31;
        unsigned long long r = __shfl_sync(0xffffffffu, (cb < 32) ? remv0 : remv1, owner);
        unsigned long long kept = 0ULL;
        if (lane == 0) {
#pragma unroll 4
            for (int jj = 0; jj < jmax; jj++) {
                if (!((r >> jj) & 1ULL)) {
                    kept |= 1ULL << jj;
                    r |= s_blk[jj];
                }
            }
        }
        kept = __shfl_sync(0xffffffffu, kept, 0);
        r = __shfl_sync(0xffffffffu, r, 0);
        if (lane == owner) { if (cb < 32) remv0 = r; else remv1 = r; }
        for (int t = lane; t < jmax; t += 32)
            keep[j0 + t] = (int)((kept >> t) & 1ULL);
        int w1 = lane, w2 = lane + 32;
        bool u1 = (w1 > cb) && (w1 < NW), u2 = (w2 > cb) && (w2 < NW);
        for (int jj = 0; jj < jmax; jj++) {
            if ((kept >> jj) & 1ULL) {
                const unsigned long long* row = mask + (size_t)(j0 + jj) * NW;
                if (u1) remv0 |= row[w1];
                if (u2) remv1 |= row[w2];
            }
        }
        __syncwarp();
    }
}

// -------- stable kept-first selection --------
__global__ void k_select1(float* __restrict__ o_props) {
    __shared__ int s_src[NPROP];
    int tid = threadIdx.x;
    if (tid < 32) {
        const int CH = NANCH / 32;
        int beg = tid * CH, end = beg + CH;
        int cnt = 0;
        for (int i = beg; i < end; i++) cnt += g_keep1[i];
        int xsc = cnt;
        for (int off = 1; off < 32; off <<= 1) {
            int v = __shfl_up_sync(0xffffffffu, xsc, off);
            if (tid >= off) xsc += v;
        }
        int excl = xsc - cnt;
        int total = __shfl_sync(0xffffffffu, xsc, 31);
        int kpos = excl;
        int npos = total + (beg - excl);
        for (int i = beg; i < end; i++) {
            int pos = g_keep1[i] ? kpos++ : npos++;
            if (pos < NPROP) s_src[pos] = i;
        }
    }
    __syncthreads();
    for (int p = tid; p < NPROP; p += 1024) {
        int i = s_src[p];
        int v = g_keep1[i];
        float4 bb = g_sb1[i];
        float px1 = v ? bb.x : 0.f, py1 = v ? bb.y : 0.f;
        float px2 = v ? bb.z : 0.f, py2 = v ? bb.w : 0.f;
        g_props[p * 4] = px1; g_props[p * 4 + 1] = py1;
        g_props[p * 4 + 2] = px2; g_props[p * 4 + 3] = py2;
        o_props[p * 4] = px1; o_props[p * 4 + 1] = py1;
        o_props[p * 4 + 2] = px2; o_props[p * 4 + 3] = py2;
        g_valid[p] = v;
    }
}

// ===================== ROI body: fp16 MMA implicit GEMM =====================
#define CROPH_H (16 * 16 * 72)
#define WSLAB_H (64 * 72)
#define SMEM_ROI_BYTES (CROPH_H * 2 + WSLAB_H * 2 + (64 + 64 + 28) * 4 + 56 * 4 + 16)

__device__ __forceinline__ void roi_body(
    int tid, float bx1, float by1, float bx2, float by2,
    const float* __restrict__ bm1, const float* __restrict__ wm2,
    const float* __restrict__ bm2,
    float* __restrict__ flat_out, float* __restrict__ maskA, float* __restrict__ maskB,
    __half* smem)
{
    __half* s_ch = smem;
    __half* s_wh = smem + CROPH_H;
    float* s_w2 = (float*)(smem + CROPH_H + WSLAB_H);
    float* s_b1 = s_w2 + 64;
    float* s_wy = s_b1 + 64;
    float* s_wx = s_wy + 14;
    int* s_y0 = (int*)(s_wx + 14);
    int* s_y1 = s_y0 + 14;
    int* s_x0 = s_y1 + 14;
    int* s_x1 = s_x0 + 14;

    int lane = tid & 31, wrp = tid >> 5;

    if (tid < 28) {
        int t = tid % 14;
        float tt = (float)t / 13.0f;
        if (tid < 14) {
            float y1n = by1 / 255.0f, y2n = by2 / 255.0f;
            float fy = (y1n + (y2n - y1n) * tt) * 15.0f;
            float y0f = fminf(fmaxf(floorf(fy), 0.f), 15.f);
            int y0 = (int)y0f;
            s_y0[t] = y0; s_y1[t] = min(y0 + 1, 15); s_wy[t] = fy - y0f;
        } else {
            float x1n = bx1 / 255.0f, x2n = bx2 / 255.0f;
            float fx = (x1n + (x2n - x1n) * tt) * 15.0f;
            float x0f = fminf(fmaxf(floorf(fx), 0.f), 15.f);
            int x0 = (int)x0f;
            s_x0[t] = x0; s_x1[t] = min(x0 + 1, 15); s_wx[t] = fx - x0f;
        }
    }
    if (tid >= 32 && tid < 96) {
        int c = tid - 32;
        s_w2[c] = wm2[c];
        s_b1[c] = bm1[c];
    }
    for (int idx = tid; idx < CROPH_H / 2; idx += 256)
        ((unsigned*)s_ch)[idx] = 0u;
    __syncthreads();

    const float4* ft4 = (const float4*)g_featT;
    for (int task = tid; task < 784; task += 256) {
        int cell = task >> 4, c4 = task & 15;
        int py = cell / 7, px = cell - py * 7;
        float4 v[2][2];
#pragma unroll
        for (int dy = 0; dy < 2; dy++)
#pragma unroll
            for (int dx = 0; dx < 2; dx++) {
                int ty = 2 * py + dy, tx = 2 * px + dx;
                int y0 = s_y0[ty], y1 = s_y1[ty], x0 = s_x0[tx], x1 = s_x1[tx];
                float wy = s_wy[ty], wx = s_wx[tx];
                float4 f00 = ft4[(y0 * 16 + x0) * 16 + c4];
                float4 f01 = ft4[(y0 * 16 + x1) * 16 + c4];
                float4 f10 = ft4[(y1 * 16 + x0) * 16 + c4];
                float4 f11 = ft4[(y1 * 16 + x1) * 16 + c4];
                float4 r;
                { float top = f00.x * (1.f - wx) + f01.x * wx;
                  float bot = f10.x * (1.f - wx) + f11.x * wx;
                  r.x = top * (1.f - wy) + bot * wy; }
                { float top = f00.y * (1.f - wx) + f01.y * wx;
                  float bot = f10.y * (1.f - wx) + f11.y * wx;
                  r.y = top * (1.f - wy) + bot * wy; }
                { float top = f00.z * (1.f - wx) + f01.z * wx;
                  float bot = f10.z * (1.f - wx) + f11.z * wx;
                  r.z = top * (1.f - wy) + bot * wy; }
                { float top = f00.w * (1.f - wx) + f01.w * wx;
                  float bot = f10.w * (1.f - wx) + f11.w * wx;
                  r.w = top * (1.f - wy) + bot * wy; }
                v[dy][dx] = r;
                __half2* dst = (__half2*)&s_ch[((ty + 1) * 16 + (tx + 1)) * 72 + c4 * 4];
                dst[0] = __floats2half2_rn(r.x, r.y);
                dst[1] = __floats2half2_rn(r.z, r.w);
            }
        flat_out[(c4 * 4 + 0) * 49 + cell] =
            fmaxf(fmaxf(v[0][0].x, v[0][1].x), fmaxf(v[1][0].x, v[1][1].x));
        flat_out[(c4 * 4 + 1) * 49 + cell] =
            fmaxf(fmaxf(v[0][0].y, v[0][1].y), fmaxf(v[1][0].y, v[1][1].y));
        flat_out[(c4 * 4 + 2) * 49 + cell] =
            fmaxf(fmaxf(v[0][0].z, v[0][1].z), fmaxf(v[1][0].z, v[1][1].z));
        flat_out[(c4 * 4 + 3) * 49 + cell] =
            fmaxf(fmaxf(v[0][0].w, v[0][1].w), fmaxf(v[1][0].w, v[1][1].w));
    }

    int g = lane >> 2, q = lane & 3;
    int pb[2][2];
#pragma unroll
    for (int mt = 0; mt < 2; mt++)
#pragma unroll
        for (int hh = 0; hh < 2; hh++) {
            int p = wrp * 32 + mt * 16 + g + hh * 8;
            if (p < 196) {
                int y = p / 14, xx = p % 14;
                pb[mt][hh] = (y * 16 + xx) * 72;
            } else pb[mt][hh] = 0;
        }

    float c[2][8][4];
#pragma unroll
    for (int mt = 0; mt < 2; mt++)
#pragma unroll
        for (int nt = 0; nt < 8; nt++)
#pragma unroll
            for (int j = 0; j < 4; j++) c[mt][nt][j] = 0.f;

    const unsigned* gwu = (const unsigned*)g_wh;
    for (int slab = 0; slab < 9; slab++) {
        __syncthreads();
        for (int f = tid; f < 2304; f += 256) {
            int oc = f / 36, icu = f - oc * 36;
            ((unsigned*)s_wh)[oc * 36 + icu] =
                (icu < 32) ? gwu[slab * 2048 + oc * 32 + icu] : 0u;
        }
        __syncthreads();
        int ky = slab / 3, kx = slab % 3;
        int off = (ky * 16 + kx) * 72;
#pragma unroll
        for (int kT = 0; kT < 4; kT++) {
            int ab = off + kT * 16 + 2 * q;
            unsigned a[2][4];
#pragma unroll
            for (int mt = 0; mt < 2; mt++) {
                a[mt][0] = *(const unsigned*)&s_ch[pb[mt][0] + ab];
                a[mt][1] = *(const unsigned*)&s_ch[pb[mt][1] + ab];
                a[mt][2] = *(const unsigned*)&s_ch[pb[mt][0] + ab + 8];
                a[mt][3] = *(const unsigned*)&s_ch[pb[mt][1] + ab + 8];
            }
            int bbase = kT * 16 + 2 * q;
#pragma unroll
            for (int nt = 0; nt < 8; nt++) {
                int oc = nt * 8 + g;
                unsigned b0 = *(const unsigned*)&s_wh[oc * 72 + bbase];
                unsigned b1 = *(const unsigned*)&s_wh[oc * 72 + bbase + 8];
                mma_f16(c[0][nt], a[0], b0, b1);
                mma_f16(c[1][nt], a[1], b0, b1);
            }
        }
    }

    float part[2][2] = {{0.f, 0.f}, {0.f, 0.f}};
#pragma unroll
    for (int nt = 0; nt < 8; nt++) {
        int col0 = nt * 8 + q * 2, col1 = col0 + 1;
        float bA = s_b1[col0], bB = s_b1[col1];
        float w20 = s_w2[col0], w21 = s_w2[col1];
#pragma unroll
        for (int mt = 0; mt < 2; mt++) {
            part[mt][0] += fmaxf(c[mt][nt][0] + bA, 0.f) * w20
                         + fmaxf(c[mt][nt][1] + bB, 0.f) * w21;
            part[mt][1] += fmaxf(c[mt][nt][2] + bA, 0.f) * w20
                         + fmaxf(c[mt][nt][3] + bB, 0.f) * w21;
        }
    }
    float b2 = bm2[0];
#pragma unroll
    for (int mt = 0; mt < 2; mt++)
#pragma unroll
        for (int hh = 0; hh < 2; hh++) {
            float v = part[mt][hh];
            v += __shfl_xor_sync(0xffffffffu, v, 1);
            v += __shfl_xor_sync(0xffffffffu, v, 2);
            int p = wrp * 32 + mt * 16 + g + hh * 8;
            if (q == 0 && p < 196) {
                float logit = b2 + v;
                maskA[p] = logit;
                maskB[p] = logit;
            }
        }
}

__global__ void __launch_bounds__(256, 2)
k_roizero(const float* __restrict__ bm1, const float* __restrict__ wm2,
          const float* __restrict__ bm2) {
    extern __shared__ __half smem_h[];
    roi_body(threadIdx.x, 0.f, 0.f, 0.f, 0.f, bm1, wm2, bm2,
             g_flatz, g_maskz, g_maskz, smem_h);
}

__global__ void __launch_bounds__(256, 2)
k_roi(const float* __restrict__ bm1, const float* __restrict__ wm2,
      const float* __restrict__ bm2, float* __restrict__ omask) {
    extern __shared__ __half smem_h[];
    int p = blockIdx.x, tid = threadIdx.x;
    if (!g_valid[p]) {
        float* fo = g_flat + (size_t)p * 3136;
        for (int idx = tid; idx < 784; idx += 256)
            ((float4*)fo)[idx] = ((const float4*)g_flatz)[idx];
        for (int pos = tid; pos < 196; pos += 256) {
            float v = g_maskz[pos];
            omask[(size_t)p * 196 + pos] = v;
            g_masks[(size_t)p * 196 + pos] = v;
        }
        return;
    }
    roi_body(tid, g_props[p * 4], g_props[p * 4 + 1], g_props[p * 4 + 2], g_props[p * 4 + 3],
             bm1, wm2, bm2,
             g_flat + (size_t)p * 3136, omask + (size_t)p * 196,
             g_masks + (size_t)p * 196, smem_h);
}

// ===== split-fp16 GEMM (fp32 A, on-the-fly split), double-buffered =====
__global__ void __launch_bounds__(256, 2)
k_gemmh(const float* __restrict__ A, const __half* __restrict__ Bh,
        const __half* __restrict__ Bl, const float* __restrict__ bias,
        float* __restrict__ C, int M, int N, int K) {
    __shared__ __half sAh[2][64][40], sAl[2][64][40], sBh[2][64][40], sBl[2][64][40];
    int tid = threadIdx.x;
    int lane = tid & 31, wrp = tid >> 5;
    int wm = wrp >> 1, wn = wrp & 1;
    int g = lane >> 2, q = lane & 3;
    int bm = blockIdx.y * 64, bn = blockIdx.x * 64;

    float acc[4][4];
#pragma unroll
    for (int nt = 0; nt < 4; nt++)
#pragma unroll
        for (int j = 0; j < 4; j++) acc[nt][j] = 0.f;

    int lr = tid >> 2, lc = (tid & 3) * 8;
    int arow = bm + lr;
    bool aok = arow < M;
    const __half* bhrow = Bh + (size_t)(bn + lr) * K;
    const __half* blrow = Bl + (size_t)(bn + lr) * K;
    const int nk = K / 32;

    {
        float4 v0 = make_float4(0.f, 0.f, 0.f, 0.f), v1 = v0;
        if (aok) {
            v0 = *(const float4*)&A[(size_t)arow * K + lc];
            v1 = *(const float4*)&A[(size_t)arow * K + lc + 4];
        }
        float vf[8] = {v0.x, v0.y, v0.z, v0.w, v1.x, v1.y, v1.z, v1.w};
#pragma unroll
        for (int j = 0; j < 8; j++) {
            __half h = __float2half_rn(vf[j]);
            sAh[0][lr][lc + j] = h;
            sAl[0][lr][lc + j] = __float2half_rn(vf[j] - __half2float(h));
        }
        *(uint4*)&sBh[0][lr][lc] = *(const uint4*)&bhrow[lc];
        *(uint4*)&sBl[0][lr][lc] = *(const uint4*)&blrow[lc];
    }
    __syncthreads();

    for (int t = 0; t < nk; t++) {
        int cur = t & 1, nxt = cur ^ 1;
        float4 v0, v1;
        uint4 wbh, wbl;
        bool havenext = (t + 1 < nk);
        if (havenext) {
            int k0 = (t + 1) * 32;
            v0 = make_float4(0.f, 0.f, 0.f, 0.f); v1 = v0;
            if (aok) {
                v0 = *(const float4*)&A[(size_t)arow * K + k0 + lc];
                v1 = *(const float4*)&A[(size_t)arow * K + k0 + lc + 4];
            }
            wbh = *(const uint4*)&bhrow[k0 + lc];
            wbl = *(const uint4*)&blrow[k0 + lc];
        }
#pragma unroll
        for (int kT = 0; kT < 2; kT++) {
            int kb = kT * 16 + 2 * q;
            int m0 = wm * 16 + g;
            unsigned ah[4], al[4];
            ah[0] = *(const unsigned*)&sAh[cur][m0][kb];
            ah[1] = *(const unsigned*)&sAh[cur][m0 + 8][kb];
            ah[2] = *(const unsigned*)&sAh[cur][m0][kb + 8];
            ah[3] = *(const unsigned*)&sAh[cur][m0 + 8][kb + 8];
            al[0] = *(const unsigned*)&sAl[cur][m0][kb];
            al[1] = *(const unsigned*)&sAl[cur][m0 + 8][kb];
            al[2] = *(const unsigned*)&sAl[cur][m0][kb + 8];
            al[3] = *(const unsigned*)&sAl[cur][m0 + 8][kb + 8];
#pragma unroll
            for (int nt = 0; nt < 4; nt++) {
                int n = wn * 32 + nt * 8 + g;
                unsigned bh0 = *(const unsigned*)&sBh[cur][n][kb];
                unsigned bh1 = *(const unsigned*)&sBh[cur][n][kb + 8];
                unsigned bl0 = *(const unsigned*)&sBl[cur][n][kb];
                unsigned bl1 = *(const unsigned*)&sBl[cur][n][kb + 8];
                mma_f16(acc[nt], ah, bh0, bh1);
                mma_f16(acc[nt], ah, bl0, bl1);
                mma_f16(acc[nt], al, bh0, bh1);
            }
        }
        if (havenext) {
            float vf[8] = {v0.x, v0.y, v0.z, v0.w, v1.x, v1.y, v1.z, v1.w};
#pragma unroll
            for (int j = 0; j < 8; j++) {
                __half h = __float2half_rn(vf[j]);
                sAh[nxt][lr][lc + j] = h;
                sAl[nxt][lr][lc + j] = __float2half_rn(vf[j] - __half2float(h));
            }
            *(uint4*)&sBh[nxt][lr][lc] = wbh;
            *(uint4*)&sBl[nxt][lr][lc] = wbl;
        }
        __syncthreads();
    }
#pragma unroll
    for (int nt = 0; nt < 4; nt++) {
        int col0 = bn + wn * 32 + nt * 8 + 2 * q;
        float b0 = bias[col0], b1 = bias[col0 + 1];
        int r0 = bm + wm * 16 + g, r1 = r0 + 8;
        if (r0 < M) {
            C[(size_t)r0 * N + col0]     = fmaxf(acc[nt][0] + b0, 0.f);
            C[(size_t)r0 * N + col0 + 1] = fmaxf(acc[nt][1] + b1, 0.f);
        }
        if (r1 < M) {
            C[(size_t)r1 * N + col0]     = fmaxf(acc[nt][2] + b0, 0.f);
            C[(size_t)r1 * N + col0 + 1] = fmaxf(acc[nt][3] + b1, 0.f);
        }
    }
}

// -------- rcnn cls/box heads + fused stage-2 decode --------
__global__ void k_rheads(const float* __restrict__ wrc, const float* __restrict__ brc,
                         const float* __restrict__ wrb, const float* __restrict__ brb,
                         float* __restrict__ o_log, float* __restrict__ o_del,
                         float* __restrict__ dets) {
    __shared__ float s6[6];
    int p = blockIdx.x;
    int w = threadIdx.x >> 5, lane = threadIdx.x & 31;
    const float* hp = g_h2 + (size_t)p * 512;
    float s = 0.f;
    if (w < 2) {
        for (int k = lane; k < 512; k += 32) s += hp[k] * wrc[k * 2 + w];
    } else {
        int j = w - 2;
        for (int k = lane; k < 512; k += 32) s += hp[k] * wrb[k * 4 + j];
    }
    for (int off = 16; off > 0; off >>= 1) s += __shfl_down_sync(0xffffffffu, s, off);
    if (lane == 0) {
        if (w < 2) {
            float v = s + brc[w];
            o_log[p * 2 + w] = v;
            g_rlogits[p * 2 + w] = v;
            s6[w] = v;
        } else {
            int j = w - 2;
            float v = s + brb[j];
            o_del[p * 4 + j] = v;
            g_rdeltas[p * 4 + j] = v;
            s6[w] = v;
        }
    }
    __syncthreads();
    if (threadIdx.x == 0) {
        float l0 = s6[0], l1 = s6[1];
        float m = fmaxf(l0, l1);
        float e0 = expf(l0 - m), e1 = expf(l1 - m);
        float sc = e1 / (e0 + e1);
        g_dscores[p] = sc;
        float x1 = g_props[p * 4], y1 = g_props[p * 4 + 1];
        float x2 = g_props[p * 4 + 2], y2 = g_props[p * 4 + 3];
        float wd = x2 - x1, h = y2 - y1;
        float cx = x1 + 0.5f * wd, cy = y1 + 0.5f * h;
        float d0 = s6[2], d1 = s6[3], d2 = s6[4], d3 = s6[5];
        float ncx = cx + d0 * wd, ncy = cy + d1 * h;
        float nw = wd * expf(d2), nh = h * expf(d3);
        dets[p * 4]     = fminf(fmaxf(ncx - 0.5f * nw, 0.f), 255.f);
        dets[p * 4 + 1] = fminf(fmaxf(ncy - 0.5f * nh, 0.f), 255.f);
        dets[p * 4 + 2] = fminf(fmaxf(ncx + 0.5f * nw, 0.f), 255.f);
        dets[p * 4 + 3] = fminf(fmaxf(ncy + 0.5f * nh, 0.f), 255.f);
        g_s2[p] = g_valid[p] ? sc : -1.0f;
    }
}

// -------- final dets/scores/keep2 + masks (fused) --------
__global__ void k_final(float* __restrict__ o_fdets, float* __restrict__ o_fsc,
                        float* __restrict__ o_keep, float* __restrict__ o_fmsk) {
    __shared__ float s_kf;
    __shared__ int s_oi;
    int r = blockIdx.x, i = threadIdx.x;
    if (i == 0) {
        int o = g_order2[r];
        int k2 = g_keep2a[r] && g_valid[o];
        float kf = k2 ? 1.f : 0.f;
        float4 d = g_sb2[r];
        o_fdets[r * 4]     = k2 ? d.x : 0.f;
        o_fdets[r * 4 + 1] = k2 ? d.y : 0.f;
        o_fdets[r * 4 + 2] = k2 ? d.z : 0.f;
        o_fdets[r * 4 + 3] = k2 ? d.w : 0.f;
        o_fsc[r] = k2 ? g_dscores[o] : 0.f;
        if (o_keep) o_keep[r] = kf;
        s_kf = kf;
        s_oi = o;
    }
    __syncthreads();
    float v = g_masks[(size_t)s_oi * 196 + i];
    float sgm = 1.f / (1.f + expf(-v));
    o_fmsk[(size_t)r * 196 + i] = sgm * s_kf;
}

// ---------------- host ----------------
extern "C" void kernel_launch(void* const* d_in, const int* in_sizes, int n_in,
                              void* d_out, int out_size) {
    const float* x      = (const float*)d_in[0];
    const float* w_bb   = (const float*)d_in[1];
    const float* b_bb   = (const float*)d_in[2];
    const float* w_rpn  = (const float*)d_in[3];
    const float* b_rpn  = (const float*)d_in[4];
    const float* w_cls  = (const float*)d_in[5];
    const float* b_cls  = (const float*)d_in[6];
    const float* w_box  = (const float*)d_in[7];
    const float* b_box  = (const float*)d_in[8];
    const float* w_fc1  = (const float*)d_in[9];
    const float* b_fc1  = (const float*)d_in[10];
    const float* w_fc2  = (const float*)d_in[11];
    const float* b_fc2  = (const float*)d_in[12];
    const float* w_rcls = (const float*)d_in[13];
    const float* b_rcls = (const float*)d_in[14];
    const float* w_rbox = (const float*)d_in[15];
    const float* b_rbox = (const float*)d_in[16];
    const float* w_m1   = (const float*)d_in[17];
    const float* b_m1   = (const float*)d_in[18];
    const float* w_m2   = (const float*)d_in[19];
    const float* b_m2   = (const float*)d_in[20];
    float* out = (float*)d_out;

    const size_t O_RPNL = 0, O_RPND = 4608, O_PROP = 13824, O_ANCH = 21824;
    const size_t O_RLOG = 31040, O_RDEL = 35040, O_RMSK = 43040;
    const size_t O_FDET = 435040, O_FMSK = 443040, O_FSC = 835040, O_KEEP = 837040;

    float *p_scores, *p_s2, *p_flat, *p_h1, *p_h2, *p_dets, *p_boxes;
    int *p_order, *p_order2, *p_keep1, *p_keep2a;
    unsigned long long *p_mask1, *p_mask2;
    __half *p_bh1, *p_bl1, *p_bh2, *p_bl2;
    cudaGetSymbolAddress((void**)&p_scores, g_scores);
    cudaGetSymbolAddress((void**)&p_order, g_order);
    cudaGetSymbolAddress((void**)&p_s2, g_s2);
    cudaGetSymbolAddress((void**)&p_order2, g_order2);
    cudaGetSymbolAddress((void**)&p_flat, g_flat);
    cudaGetSymbolAddress((void**)&p_h1, g_h1);
    cudaGetSymbolAddress((void**)&p_h2, g_h2);
    cudaGetSymbolAddress((void**)&p_dets, g_dets);
    cudaGetSymbolAddress((void**)&p_boxes, g_boxes);
    cudaGetSymbolAddress((void**)&p_keep1, g_keep1);
    cudaGetSymbolAddress((void**)&p_keep2a, g_keep2a);
    cudaGetSymbolAddress((void**)&p_mask1, g_mask1);
    cudaGetSymbolAddress((void**)&p_mask2, g_mask2);
    cudaGetSymbolAddress((void**)&p_bh1, g_bh1);
    cudaGetSymbolAddress((void**)&p_bl1, g_bl1);
    cudaGetSymbolAddress((void**)&p_bh2, g_bh2);
    cudaGetSymbolAddress((void**)&p_bl2, g_bl2);

    cudaFuncSetAttribute(k_roi, cudaFuncAttributeMaxDynamicSharedMemorySize, SMEM_ROI_BYTES);
    cudaFuncSetAttribute(k_roizero, cudaFuncAttributeMaxDynamicSharedMemorySize, SMEM_ROI_BYTES);

    float4* p_sb1; float* p_sa1; float4* p_sb2; float* p_sa2;
    cudaGetSymbolAddress((void**)&p_sb1, g_sb1);
    cudaGetSymbolAddress((void**)&p_sa1, g_sa1);
    cudaGetSymbolAddress((void**)&p_sb2, g_sb2);
    cudaGetSymbolAddress((void**)&p_sa2, g_sa2);

    k_backbone<<<256, 256>>>(x, w_bb, b_bb);
    k_packwh<<<(9 * 64 * 64 + 255) / 256, 256>>>(w_m1);
    k_packw<<<(64 * 64 * 12 + 255) / 256, 256>>>(w_rpn);
    {
        dim3 tb(32, 8);
        k_packBt<<<dim3(512 / 32, 3136 / 32), tb>>>(w_fc1, p_bh1, p_bl1, 3136, 512);
        k_packBt<<<dim3(512 / 32, 512 / 32), tb>>>(w_fc2, p_bh2, p_bl2, 512, 512);
    }
    k_roizero<<<1, 256, SMEM_ROI_BYTES>>>(b_m1, w_m2, b_m2);
    k_rpnconv<<<256, 512>>>(b_rpn);
    k_heads1<<<18, 128>>>(w_cls, b_cls, w_box, b_box,
                          out + O_RPNL, out + O_RPND, out + O_ANCH);
    k_sort<4096><<<1, 1024>>>(p_scores, NANCH, p_order, p_boxes, p_sb1, p_sa1);
    k_ioumask<NANCH, NW1><<<dim3(NW1, NW1), 64>>>(p_sb1, p_sa1, p_mask1, 0.5f);
    k_nmsreduce<NANCH, NW1><<<1, 32>>>(p_mask1, p_keep1);
    k_select1<<<1, 1024>>>(out + O_PROP);
    k_roi<<<NPROP, 256, SMEM_ROI_BYTES>>>(b_m1, w_m2, b_m2, out + O_RMSK);

    dim3 gfc(8, 32);
    k_gemmh<<<gfc, 256>>>(p_flat, p_bh1, p_bl1, b_fc1, p_h1, NPROP, 512, 3136);
    k_gemmh<<<gfc, 256>>>(p_h1, p_bh2, p_bl2, b_fc2, p_h2, NPROP, 512, 512);
    k_rheads<<<NPROP, 192>>>(w_rcls, b_rcls, w_rbox, b_rbox,
                             out + O_RLOG, out + O_RDEL, p_dets);
    k_sort<2048><<<1, 1024>>>(p_s2, NPROP, p_order2, p_dets, p_sb2, p_sa2);
    k_ioumask<NPROP, NW2><<<dim3(NW2, NW2), 64>>>(p_sb2, p_sa2, p_mask2, 0.3f);
    k_nmsreduce<NPROP, NW2><<<1, 32>>>(p_mask2, p_keep2a);
    float* o_keep = (out_size >= (int)(O_KEEP + NPROP)) ? (out + O_KEEP) : nullptr;
    k_final<<<NPROP, 196>>>(out + O_FDET, out + O_FSC, o_keep, out + O_FMSK);
}

// round 16
// speedup vs baseline: 1.4782x; 1.0165x over previous
#include <cuda_runtime.h>
#include <cuda_fp16.h>
#include <stdint.h>
#include <math.h>

#define NANCH 2304
#define NPROP 2000
#define NW1 36
#define NW2 32

// ---------------- scratch (device globals; no allocation) ----------------
__device__ float g_feat[64 * 256];
__device__ float g_featT[256 * 64];
__device__ float g_featP[64 * 18 * 18];
__device__ float g_hrpn[64 * 256];
__device__ float g_scores[NANCH];
__device__ float g_boxes[NANCH * 4];
__device__ int   g_order[NANCH];
__device__ float g_props[NPROP * 4];
__device__ int   g_valid[NPROP];
__device__ float g_flat[NPROP * 3136];
__device__ float g_h1[NPROP * 512];
__device__ float g_h2[NPROP * 512];
__device__ float g_rlogits[NPROP * 2];
__device__ float g_rdeltas[NPROP * 4];
__device__ float g_dscores[NPROP];
__device__ float g_s2[NPROP];
__device__ int   g_order2[NPROP];
__device__ float g_masks[NPROP * 196];
__device__ float g_dets[NPROP * 4];
__device__ unsigned short g_wh[9 * 64 * 64];     // mask-conv weights fp16 [slab][oc][ic]
__device__ float g_wpack[64 * 64 * 12];          // rpn-conv weights float4-aligned
__device__ float g_flatz[3136];
__device__ float g_maskz[196];
// split-fp16 FC weights, transposed [N][K]
__device__ __half g_bh1[512 * 3136];
__device__ __half g_bl1[512 * 3136];
__device__ __half g_bh2[512 * 512];
__device__ __half g_bl2[512 * 512];
// NMS scratch
__device__ float4 g_sb1[NANCH];
__device__ float  g_sa1[NANCH];
__device__ unsigned long long g_mask1[(size_t)NANCH * NW1];
__device__ int    g_keep1[NANCH];
__device__ float4 g_sb2[NPROP];
__device__ float  g_sa2[NPROP];
__device__ unsigned long long g_mask2[(size_t)NPROP * NW2];
__device__ int    g_keep2a[NPROP];

__device__ __forceinline__ void mma_f16(float* c, const unsigned* a,
                                        unsigned b0, unsigned b1) {
    asm volatile(
        "mma.sync.aligned.m16n8k16.row.col.f32.f16.f16.f32 "
        "{%0,%1,%2,%3},{%4,%5,%6,%7},{%8,%9},{%0,%1,%2,%3};"
        : "+f"(c[0]), "+f"(c[1]), "+f"(c[2]), "+f"(c[3])
        : "r"(a[0]), "r"(a[1]), "r"(a[2]), "r"(a[3]), "r"(b0), "r"(b1));
}

// ---------------- backbone ----------------
__global__ void k_backbone(const float* __restrict__ x, const float* __restrict__ w,
                           const float* __restrict__ b) {
    __shared__ float patch[768];
    __shared__ float part[256];
    int pos = blockIdx.x;
    int h = pos >> 4, wq = pos & 15;
    int tid = threadIdx.x;
    for (int k = tid; k < 768; k += 256) {
        int ic = k >> 8, r = k & 255, iy = r >> 4, ix = r & 15;
        patch[k] = x[ic * 65536 + (h * 16 + iy) * 256 + (wq * 16 + ix)];
    }
    __syncthreads();
    int oc = tid & 63, ch = tid >> 6;
    const float* wp = w + oc * 768 + ch * 192;
    const float* pp = patch + ch * 192;
    float a0 = 0.f, a1 = 0.f;
#pragma unroll 8
    for (int k = 0; k < 192; k += 2) { a0 += pp[k] * wp[k]; a1 += pp[k + 1] * wp[k + 1]; }
    part[tid] = a0 + a1;
    __syncthreads();
    if (tid < 64) {
        float s = b[tid] + part[tid] + part[tid + 64] + part[tid + 128] + part[tid + 192];
        float v = fmaxf(s, 0.f);
        g_feat[tid * 256 + pos] = v;
        g_featT[pos * 64 + tid] = v;
        g_featP[tid * 324 + (h + 1) * 18 + (wq + 1)] = v;
    }
}

// -------- pack rpn weights [oc][ic][9] -> [oc][ic][12] (float4-aligned) ----
__global__ void k_packw(const float* __restrict__ w) {
    int i = blockIdx.x * blockDim.x + threadIdx.x;
    if (i >= 64 * 64 * 12) return;
    int pair = i / 12, q = i % 12;
    g_wpack[i] = (q < 9) ? w[pair * 9 + q] : 0.f;
}

// ---------------- rpn conv 3x3 SAME, relu (8-way splitK, 512 thr) ----------------
__global__ void k_rpnconv(const float* __restrict__ b) {
    __shared__ float s_f[576];
    __shared__ float part[512];
    int pos = blockIdx.x;
    int y = pos >> 4, xq = pos & 15;
    int tid = threadIdx.x;
    for (int k = tid; k < 576; k += 512) {
        int ic = k / 9, r = k % 9, ky = r / 3, kx = r % 3;
        s_f[k] = g_featP[ic * 324 + (y + ky) * 18 + (xq + kx)];
    }
    __syncthreads();
    int oc = tid & 63, ch = tid >> 6;
    const float4* wp4 = (const float4*)g_wpack;
    float acc0 = 0.f, acc1 = 0.f;
    for (int icl = 0; icl < 8; icl += 2) {
        int ic = ch * 8 + icl;
        float4 A0 = wp4[(oc * 64 + ic) * 3], A1 = wp4[(oc * 64 + ic) * 3 + 1],
               A2 = wp4[(oc * 64 + ic) * 3 + 2];
        float4 B0 = wp4[(oc * 64 + ic + 1) * 3], B1 = wp4[(oc * 64 + ic + 1) * 3 + 1],
               B2 = wp4[(oc * 64 + ic + 1) * 3 + 2];
        float wAr[9] = {A0.x, A0.y, A0.z, A0.w, A1.x, A1.y, A1.z, A1.w, A2.x};
        float wBr[9] = {B0.x, B0.y, B0.z, B0.w, B1.x, B1.y, B1.z, B1.w, B2.x};
        const float* f0 = s_f + ic * 9;
#pragma unroll
        for (int k = 0; k < 9; k++) {
            acc0 += f0[k] * wAr[k];
            acc1 += f0[9 + k] * wBr[k];
        }
    }
    part[tid] = acc0 + acc1;
    __syncthreads();
    if (tid < 64) {
        float s = b[tid];
#pragma unroll
        for (int j = 0; j < 8; j++) s += part[tid + 64 * j];
        g_hrpn[tid * 256 + pos] = fmaxf(s, 0.f);
    }
}

// -------- rpn heads (1x1), anchors, softmax score, decode, clip --------
__global__ void k_heads1(const float* __restrict__ wc, const float* __restrict__ bc,
                         const float* __restrict__ wb, const float* __restrict__ bb,
                         float* __restrict__ o_logits, float* __restrict__ o_deltas,
                         float* __restrict__ o_anch) {
    int i = blockIdx.x * blockDim.x + threadIdx.x;
    if (i >= NANCH) return;
    int cell = i / 9, a = i % 9;
    float l0 = bc[a * 2], l1 = bc[a * 2 + 1];
    float d0 = bb[a * 4], d1 = bb[a * 4 + 1], d2 = bb[a * 4 + 2], d3 = bb[a * 4 + 3];
    for (int ic = 0; ic < 64; ic++) {
        float f = g_hrpn[ic * 256 + cell];
        l0 += f * wc[(a * 2) * 64 + ic];
        l1 += f * wc[(a * 2 + 1) * 64 + ic];
        d0 += f * wb[(a * 4) * 64 + ic];
        d1 += f * wb[(a * 4 + 1) * 64 + ic];
        d2 += f * wb[(a * 4 + 2) * 64 + ic];
        d3 += f * wb[(a * 4 + 3) * 64 + ic];
    }
    o_logits[i * 2] = l0; o_logits[i * 2 + 1] = l1;
    o_deltas[i * 4] = d0; o_deltas[i * 4 + 1] = d1;
    o_deltas[i * 4 + 2] = d2; o_deltas[i * 4 + 3] = d3;
    float m = fmaxf(l0, l1);
    float e0 = expf(l0 - m), e1 = expf(l1 - m);
    g_scores[i] = e1 / (e0 + e1);

    const float S[3] = {32.f, 64.f, 128.f};
    const float R[3] = {0.5f, 1.f, 2.f};
    int h = cell >> 4, wq = cell & 15;
    float s = S[a / 3], r = R[a % 3];
    float ws = s * sqrtf(r), hs = s / sqrtf(r);
    float cx = (wq + 0.5f) * 16.f, cy = (h + 0.5f) * 16.f;
    float ax1 = cx - ws * 0.5f, ay1 = cy - hs * 0.5f;
    float ax2 = cx + ws * 0.5f, ay2 = cy + hs * 0.5f;
    o_anch[i * 4] = ax1; o_anch[i * 4 + 1] = ay1;
    o_anch[i * 4 + 2] = ax2; o_anch[i * 4 + 3] = ay2;

    float aw = ax2 - ax1, ah = ay2 - ay1;
    float acx = ax1 + 0.5f * aw, acy = ay1 + 0.5f * ah;
    float ncx = acx + d0 * aw, ncy = acy + d1 * ah;
    float nw = aw * expf(d2), nh = ah * expf(d3);
    g_boxes[i * 4]     = fminf(fmaxf(ncx - 0.5f * nw, 0.f), 255.f);
    g_boxes[i * 4 + 1] = fminf(fmaxf(ncy - 0.5f * nh, 0.f), 255.f);
    g_boxes[i * 4 + 2] = fminf(fmaxf(ncx + 0.5f * nw, 0.f), 255.f);
    g_boxes[i * 4 + 3] = fminf(fmaxf(ncy + 0.5f * nh, 0.f), 255.f);
}

// -------- pack mask-conv weights fp16 [slab][oc][ic] ----
__global__ void k_packwh(const float* __restrict__ w) {
    int i = blockIdx.x * blockDim.x + threadIdx.x;
    if (i >= 9 * 64 * 64) return;
    int slab = i >> 12, r = i & 4095, oc = r >> 6, ic = r & 63;
    g_wh[i] = __half_as_ushort(__float2half_rn(w[oc * 576 + ic * 9 + slab]));
}

// -------- tiled transpose pack: w[K][N] -> Bh/Bl [N][K] split-fp16 ----
__global__ void k_packBt(const float* __restrict__ w, __half* __restrict__ Bh,
                         __half* __restrict__ Bl, int K, int N) {
    __shared__ float tile[32][33];
    int kb = blockIdx.y * 32, nb = blockIdx.x * 32;
    int tx = threadIdx.x, ty = threadIdx.y;   // 32 x 8
#pragma unroll
    for (int i = 0; i < 32; i += 8) {
        int k = kb + ty + i, n = nb + tx;
        tile[ty + i][tx] = (k < K && n < N) ? w[(size_t)k * N + n] : 0.f;
    }
    __syncthreads();
#pragma unroll
    for (int i = 0; i < 32; i += 8) {
        int n = nb + ty + i, k = kb + tx;
        if (n < N && k < K) {
            float x = tile[tx][ty + i];
            __half h = __float2half_rn(x);
            Bh[(size_t)n * K + k] = h;
            Bl[(size_t)n * K + k] = __float2half_rn(x - __half2float(h));
        }
    }
}

// -------- single-block bitonic sort + fused box gather --------
template <int SIZE>
__global__ void k_sort(const float* __restrict__ sc, int n, int* __restrict__ ord,
                       const float* __restrict__ boxes, float4* __restrict__ sb,
                       float* __restrict__ sa) {
    __shared__ unsigned long long k[SIZE];
    int tid = threadIdx.x;
    for (int i = tid; i < SIZE; i += 1024) {
        if (i < n) {
            unsigned u = __float_as_uint(sc[i]);
            unsigned o = (u & 0x80000000u) ? ~u : (u | 0x80000000u);
            k[i] = ((unsigned long long)(~o) << 32) | (unsigned)i;
        } else k[i] = 0xFFFFFFFFFFFFFFFFULL;
    }
    __syncthreads();
    for (int kk = 2; kk <= SIZE; kk <<= 1) {
        for (int j = kk >> 1; j > 0; j >>= 1) {
            for (int i = tid; i < SIZE; i += 1024) {
                int ixj = i ^ j;
                if (ixj > i) {
                    bool up = ((i & kk) == 0);
                    unsigned long long a = k[i], b = k[ixj];
                    if ((a > b) == up) { k[i] = b; k[ixj] = a; }
                }
            }
            __syncthreads();
        }
    }
    for (int i = tid; i < n; i += 1024) {
        int idx = (int)(k[i] & 0xFFFFFFFFu);
        ord[i] = idx;
        float4 b = *(const float4*)&boxes[idx * 4];
        sb[i] = b;
        sa[i] = fmaxf(b.z - b.x, 0.f) * fmaxf(b.w - b.y, 0.f);
    }
}

// -------- IoU bitmask matrix --------
template <int N, int NW>
__global__ void k_ioumask(const float4* __restrict__ sb, const float* __restrict__ sa,
                          unsigned long long* __restrict__ mask, float thr) {
    __shared__ float4 cbx[64];
    __shared__ float car[64];
    int rb = blockIdx.y, cb = blockIdx.x;
    int t = threadIdx.x;
    int j0 = cb * 64;
    if (j0 + t < N) { cbx[t] = sb[j0 + t]; car[t] = sa[j0 + t]; }
    __syncthreads();
    int i = rb * 64 + t;
    if (i >= N) return;
    float4 bi = sb[i];
    float ai = sa[i];
    unsigned long long m = 0;
    int jmax = min(64, N - j0);
    for (int jj = 0; jj < jmax; jj++) {
        int j = j0 + jj;
        if (j <= i) continue;
        float xx1 = fmaxf(bi.x, cbx[jj].x), yy1 = fmaxf(bi.y, cbx[jj].y);
        float xx2 = fminf(bi.z, cbx[jj].z), yy2 = fminf(bi.w, cbx[jj].w);
        float inter = fmaxf(xx2 - xx1, 0.f) * fmaxf(yy2 - yy1, 0.f);
        float iou = inter / (ai + car[jj] - inter + 1e-8f);
        if (iou > thr) m |= 1ULL << jj;
    }
    mask[(size_t)i * NW + cb] = m;
}

// -------- chunked exact greedy reduce --------
template <int N, int NW>
__global__ void k_nmsreduce(const unsigned long long* __restrict__ mask,
                            int* __restrict__ keep) {
    __shared__ unsigned long long s_blk[64];
    int lane = threadIdx.x;
    unsigned long long remv0 = 0ULL, remv1 = 0ULL;
    const int NC = (N + 63) / 64;
    for (int cb = 0; cb < NC; cb++) {
        int j0 = cb * 64;
        int jmax = min(64, N - j0);
        for (int t = lane; t < jmax; t += 32)
            s_blk[t] = mask[(size_t)(j0 + t) * NW + cb];
        __syncwarp();
        int owner = cb & 31;
        unsigned long long r = __shfl_sync(0xffffffffu, (cb < 32) ? remv0 : remv1, owner);
        unsigned long long kept = 0ULL;
        if (lane == 0) {
#pragma unroll 4
            for (int jj = 0; jj < jmax; jj++) {
                if (!((r >> jj) & 1ULL)) {
                    kept |= 1ULL << jj;
                    r |= s_blk[jj];
                }
            }
        }
        kept = __shfl_sync(0xffffffffu, kept, 0);
        r = __shfl_sync(0xffffffffu, r, 0);
        if (lane == owner) { if (cb < 32) remv0 = r; else remv1 = r; }
        for (int t = lane; t < jmax; t += 32)
            keep[j0 + t] = (int)((kept >> t) & 1ULL);
        int w1 = lane, w2 = lane + 32;
        bool u1 = (w1 > cb) && (w1 < NW), u2 = (w2 > cb) && (w2 < NW);
        for (int jj = 0; jj < jmax; jj++) {
            if ((kept >> jj) & 1ULL) {
                const unsigned long long* row = mask + (size_t)(j0 + jj) * NW;
                if (u1) remv0 |= row[w1];
                if (u2) remv1 |= row[w2];
            }
        }
        __syncwarp();
    }
}

// -------- stable kept-first selection --------
__global__ void k_select1(float* __restrict__ o_props) {
    __shared__ int s_src[NPROP];
    int tid = threadIdx.x;
    if (tid < 32) {
        const int CH = NANCH / 32;
        int beg = tid * CH, end = beg + CH;
        int cnt = 0;
        for (int i = beg; i < end; i++) cnt += g_keep1[i];
        int xsc = cnt;
        for (int off = 1; off < 32; off <<= 1) {
            int v = __shfl_up_sync(0xffffffffu, xsc, off);
            if (tid >= off) xsc += v;
        }
        int excl = xsc - cnt;
        int total = __shfl_sync(0xffffffffu, xsc, 31);
        int kpos = excl;
        int npos = total + (beg - excl);
        for (int i = beg; i < end; i++) {
            int pos = g_keep1[i] ? kpos++ : npos++;
            if (pos < NPROP) s_src[pos] = i;
        }
    }
    __syncthreads();
    for (int p = tid; p < NPROP; p += 1024) {
        int i = s_src[p];
        int v = g_keep1[i];
        float4 bb = g_sb1[i];
        float px1 = v ? bb.x : 0.f, py1 = v ? bb.y : 0.f;
        float px2 = v ? bb.z : 0.f, py2 = v ? bb.w : 0.f;
        g_props[p * 4] = px1; g_props[p * 4 + 1] = py1;
        g_props[p * 4 + 2] = px2; g_props[p * 4 + 3] = py2;
        o_props[p * 4] = px1; o_props[p * 4 + 1] = py1;
        o_props[p * 4 + 2] = px2; o_props[p * 4 + 3] = py2;
        g_valid[p] = v;
    }
}

// ===================== ROI body: fp16 MMA, double-buffered weight slabs =====
#define CROPH_H (16 * 16 * 72)
#define WSLAB_H (64 * 72)
#define SMEM_ROI_BYTES (CROPH_H * 2 + 2 * WSLAB_H * 2 + (64 + 64 + 28) * 4 + 56 * 4 + 16)

__device__ __forceinline__ void roi_body(
    int tid, float bx1, float by1, float bx2, float by2,
    const float* __restrict__ bm1, const float* __restrict__ wm2,
    const float* __restrict__ bm2,
    float* __restrict__ flat_out, float* __restrict__ maskA, float* __restrict__ maskB,
    __half* smem)
{
    __half* s_ch = smem;
    __half* s_wh = smem + CROPH_H;             // 2 x WSLAB_H halves
    float* s_w2 = (float*)(smem + CROPH_H + 2 * WSLAB_H);
    float* s_b1 = s_w2 + 64;
    float* s_wy = s_b1 + 64;
    float* s_wx = s_wy + 14;
    int* s_y0 = (int*)(s_wx + 14);
    int* s_y1 = s_y0 + 14;
    int* s_x0 = s_y1 + 14;
    int* s_x1 = s_x0 + 14;

    int lane = tid & 31, wrp = tid >> 5;

    if (tid < 28) {
        int t = tid % 14;
        float tt = (float)t / 13.0f;
        if (tid < 14) {
            float y1n = by1 / 255.0f, y2n = by2 / 255.0f;
            float fy = (y1n + (y2n - y1n) * tt) * 15.0f;
            float y0f = fminf(fmaxf(floorf(fy), 0.f), 15.f);
            int y0 = (int)y0f;
            s_y0[t] = y0; s_y1[t] = min(y0 + 1, 15); s_wy[t] = fy - y0f;
        } else {
            float x1n = bx1 / 255.0f, x2n = bx2 / 255.0f;
            float fx = (x1n + (x2n - x1n) * tt) * 15.0f;
            float x0f = fminf(fmaxf(floorf(fx), 0.f), 15.f);
            int x0 = (int)x0f;
            s_x0[t] = x0; s_x1[t] = min(x0 + 1, 15); s_wx[t] = fx - x0f;
        }
    }
    if (tid >= 32 && tid < 96) {
        int c = tid - 32;
        s_w2[c] = wm2[c];
        s_b1[c] = bm1[c];
    }
    for (int idx = tid; idx < CROPH_H / 2; idx += 256)
        ((unsigned*)s_ch)[idx] = 0u;
    __syncthreads();

    const float4* ft4 = (const float4*)g_featT;
    for (int task = tid; task < 784; task += 256) {
        int cell = task >> 4, c4 = task & 15;
        int py = cell / 7, px = cell - py * 7;
        float4 v[2][2];
#pragma unroll
        for (int dy = 0; dy < 2; dy++)
#pragma unroll
            for (int dx = 0; dx < 2; dx++) {
                int ty = 2 * py + dy, tx = 2 * px + dx;
                int y0 = s_y0[ty], y1 = s_y1[ty], x0 = s_x0[tx], x1 = s_x1[tx];
                float wy = s_wy[ty], wx = s_wx[tx];
                float4 f00 = ft4[(y0 * 16 + x0) * 16 + c4];
                float4 f01 = ft4[(y0 * 16 + x1) * 16 + c4];
                float4 f10 = ft4[(y1 * 16 + x0) * 16 + c4];
                float4 f11 = ft4[(y1 * 16 + x1) * 16 + c4];
                float4 r;
                { float top = f00.x * (1.f - wx) + f01.x * wx;
                  float bot = f10.x * (1.f - wx) + f11.x * wx;
                  r.x = top * (1.f - wy) + bot * wy; }
                { float top = f00.y * (1.f - wx) + f01.y * wx;
                  float bot = f10.y * (1.f - wx) + f11.y * wx;
                  r.y = top * (1.f - wy) + bot * wy; }
                { float top = f00.z * (1.f - wx) + f01.z * wx;
                  float bot = f10.z * (1.f - wx) + f11.z * wx;
                  r.z = top * (1.f - wy) + bot * wy; }
                { float top = f00.w * (1.f - wx) + f01.w * wx;
                  float bot = f10.w * (1.f - wx) + f11.w * wx;
                  r.w = top * (1.f - wy) + bot * wy; }
                v[dy][dx] = r;
                __half2* dst = (__half2*)&s_ch[((ty + 1) * 16 + (tx + 1)) * 72 + c4 * 4];
                dst[0] = __floats2half2_rn(r.x, r.y);
                dst[1] = __floats2half2_rn(r.z, r.w);
            }
        flat_out[(c4 * 4 + 0) * 49 + cell] =
            fmaxf(fmaxf(v[0][0].x, v[0][1].x), fmaxf(v[1][0].x, v[1][1].x));
        flat_out[(c4 * 4 + 1) * 49 + cell] =
            fmaxf(fmaxf(v[0][0].y, v[0][1].y), fmaxf(v[1][0].y, v[1][1].y));
        flat_out[(c4 * 4 + 2) * 49 + cell] =
            fmaxf(fmaxf(v[0][0].z, v[0][1].z), fmaxf(v[1][0].z, v[1][1].z));
        flat_out[(c4 * 4 + 3) * 49 + cell] =
            fmaxf(fmaxf(v[0][0].w, v[0][1].w), fmaxf(v[1][0].w, v[1][1].w));
    }

    int g = lane >> 2, q = lane & 3;
    int pb[2][2];
#pragma unroll
    for (int mt = 0; mt < 2; mt++)
#pragma unroll
        for (int hh = 0; hh < 2; hh++) {
            int p = wrp * 32 + mt * 16 + g + hh * 8;
            if (p < 196) {
                int y = p / 14, xx = p % 14;
                pb[mt][hh] = (y * 16 + xx) * 72;
            } else pb[mt][hh] = 0;
        }

    float c[2][8][4];
#pragma unroll
    for (int mt = 0; mt < 2; mt++)
#pragma unroll
        for (int nt = 0; nt < 8; nt++)
#pragma unroll
            for (int j = 0; j < 4; j++) c[mt][nt][j] = 0.f;

    const unsigned* gwu = (const unsigned*)g_wh;
    // per-thread staging indices (9 uints per thread cover 2304 uints)
    int sidx[9], gofs[9];
#pragma unroll
    for (int j = 0; j < 9; j++) {
        int f = tid + j * 256;
        int oc = f / 36, icu = f - oc * 36;
        sidx[j] = oc * 36 + icu;
        gofs[j] = (icu < 32) ? (oc * 32 + icu) : -1;
    }
    unsigned wreg[9];
    // preload slab 0
#pragma unroll
    for (int j = 0; j < 9; j++)
        wreg[j] = (gofs[j] >= 0) ? gwu[gofs[j]] : 0u;
    {
        unsigned* buf0 = (unsigned*)s_wh;
#pragma unroll
        for (int j = 0; j < 9; j++) buf0[sidx[j]] = wreg[j];
    }
    __syncthreads();   // covers crop writes + slab0 staging

    for (int slab = 0; slab < 9; slab++) {
        bool havenext = (slab + 1 < 9);
        if (havenext) {
            const unsigned* gsl = gwu + (slab + 1) * 2048;
#pragma unroll
            for (int j = 0; j < 9; j++)
                wreg[j] = (gofs[j] >= 0) ? gsl[gofs[j]] : 0u;
        }
        const __half* wbuf = s_wh + (slab & 1) * WSLAB_H;
        int ky = slab / 3, kx = slab % 3;
        int off = (ky * 16 + kx) * 72;
#pragma unroll
        for (int kT = 0; kT < 4; kT++) {
            int ab = off + kT * 16 + 2 * q;
            unsigned a[2][4];
#pragma unroll
            for (int mt = 0; mt < 2; mt++) {
                a[mt][0] = *(const unsigned*)&s_ch[pb[mt][0] + ab];
                a[mt][1] = *(const unsigned*)&s_ch[pb[mt][1] + ab];
                a[mt][2] = *(const unsigned*)&s_ch[pb[mt][0] + ab + 8];
                a[mt][3] = *(const unsigned*)&s_ch[pb[mt][1] + ab + 8];
            }
            int bbase = kT * 16 + 2 * q;
#pragma unroll
            for (int nt = 0; nt < 8; nt++) {
                int oc = nt * 8 + g;
                unsigned b0 = *(const unsigned*)&wbuf[oc * 72 + bbase];
                unsigned b1 = *(const unsigned*)&wbuf[oc * 72 + bbase + 8];
                mma_f16(c[0][nt], a[0], b0, b1);
                mma_f16(c[1][nt], a[1], b0, b1);
            }
        }
        if (havenext) {
            unsigned* nbuf = (unsigned*)(s_wh + ((slab + 1) & 1) * WSLAB_H);
#pragma unroll
            for (int j = 0; j < 9; j++) nbuf[sidx[j]] = wreg[j];
        }
        __syncthreads();
    }

    float part[2][2] = {{0.f, 0.f}, {0.f, 0.f}};
#pragma unroll
    for (int nt = 0; nt < 8; nt++) {
        int col0 = nt * 8 + q * 2, col1 = col0 + 1;
        float bA = s_b1[col0], bB = s_b1[col1];
        float w20 = s_w2[col0], w21 = s_w2[col1];
#pragma unroll
        for (int mt = 0; mt < 2; mt++) {
            part[mt][0] += fmaxf(c[mt][nt][0] + bA, 0.f) * w20
                         + fmaxf(c[mt][nt][1] + bB, 0.f) * w21;
            part[mt][1] += fmaxf(c[mt][nt][2] + bA, 0.f) * w20
                         + fmaxf(c[mt][nt][3] + bB, 0.f) * w21;
        }
    }
    float b2 = bm2[0];
#pragma unroll
    for (int mt = 0; mt < 2; mt++)
#pragma unroll
        for (int hh = 0; hh < 2; hh++) {
            float v = part[mt][hh];
            v += __shfl_xor_sync(0xffffffffu, v, 1);
            v += __shfl_xor_sync(0xffffffffu, v, 2);
            int p = wrp * 32 + mt * 16 + g + hh * 8;
            if (q == 0 && p < 196) {
                float logit = b2 + v;
                maskA[p] = logit;
                maskB[p] = logit;
            }
        }
}

__global__ void __launch_bounds__(256, 2)
k_roizero(const float* __restrict__ bm1, const float* __restrict__ wm2,
          const float* __restrict__ bm2) {
    extern __shared__ __half smem_h[];
    roi_body(threadIdx.x, 0.f, 0.f, 0.f, 0.f, bm1, wm2, bm2,
             g_flatz, g_maskz, g_maskz, smem_h);
}

__global__ void __launch_bounds__(256, 2)
k_roi(const float* __restrict__ bm1, const float* __restrict__ wm2,
      const float* __restrict__ bm2, float* __restrict__ omask) {
    extern __shared__ __half smem_h[];
    int p = blockIdx.x, tid = threadIdx.x;
    if (!g_valid[p]) {
        float* fo = g_flat + (size_t)p * 3136;
        for (int idx = tid; idx < 784; idx += 256)
            ((float4*)fo)[idx] = ((const float4*)g_flatz)[idx];
        for (int pos = tid; pos < 196; pos += 256) {
            float v = g_maskz[pos];
            omask[(size_t)p * 196 + pos] = v;
            g_masks[(size_t)p * 196 + pos] = v;
        }
        return;
    }
    roi_body(tid, g_props[p * 4], g_props[p * 4 + 1], g_props[p * 4 + 2], g_props[p * 4 + 3],
             bm1, wm2, bm2,
             g_flat + (size_t)p * 3136, omask + (size_t)p * 196,
             g_masks + (size_t)p * 196, smem_h);
}

// ===== split-fp16 GEMM (fp32 A, on-the-fly split), double-buffered =====
__global__ void __launch_bounds__(256, 2)
k_gemmh(const float* __restrict__ A, const __half* __restrict__ Bh,
        const __half* __restrict__ Bl, const float* __restrict__ bias,
        float* __restrict__ C, int M, int N, int K) {
    __shared__ __half sAh[2][64][40], sAl[2][64][40], sBh[2][64][40], sBl[2][64][40];
    int tid = threadIdx.x;
    int lane = tid & 31, wrp = tid >> 5;
    int wm = wrp >> 1, wn = wrp & 1;
    int g = lane >> 2, q = lane & 3;
    int bm = blockIdx.y * 64, bn = blockIdx.x * 64;

    float acc[4][4];
#pragma unroll
    for (int nt = 0; nt < 4; nt++)
#pragma unroll
        for (int j = 0; j < 4; j++) acc[nt][j] = 0.f;

    int lr = tid >> 2, lc = (tid & 3) * 8;
    int arow = bm + lr;
    bool aok = arow < M;
    const __half* bhrow = Bh + (size_t)(bn + lr) * K;
    const __half* blrow = Bl + (size_t)(bn + lr) * K;
    const int nk = K / 32;

    {
        float4 v0 = make_float4(0.f, 0.f, 0.f, 0.f), v1 = v0;
        if (aok) {
            v0 = *(const float4*)&A[(size_t)arow * K + lc];
            v1 = *(const float4*)&A[(size_t)arow * K + lc + 4];
        }
        float vf[8] = {v0.x, v0.y, v0.z, v0.w, v1.x, v1.y, v1.z, v1.w};
#pragma unroll
        for (int j = 0; j < 8; j++) {
            __half h = __float2half_rn(vf[j]);
            sAh[0][lr][lc + j] = h;
            sAl[0][lr][lc + j] = __float2half_rn(vf[j] - __half2float(h));
        }
        *(uint4*)&sBh[0][lr][lc] = *(const uint4*)&bhrow[lc];
        *(uint4*)&sBl[0][lr][lc] = *(const uint4*)&blrow[lc];
    }
    __syncthreads();

    for (int t = 0; t < nk; t++) {
        int cur = t & 1, nxt = cur ^ 1;
        float4 v0, v1;
        uint4 wbh, wbl;
        bool havenext = (t + 1 < nk);
        if (havenext) {
            int k0 = (t + 1) * 32;
            v0 = make_float4(0.f, 0.f, 0.f, 0.f); v1 = v0;
            if (aok) {
                v0 = *(const float4*)&A[(size_t)arow * K + k0 + lc];
                v1 = *(const float4*)&A[(size_t)arow * K + k0 + lc + 4];
            }
            wbh = *(const uint4*)&bhrow[k0 + lc];
            wbl = *(const uint4*)&blrow[k0 + lc];
        }
#pragma unroll
        for (int kT = 0; kT < 2; kT++) {
            int kb = kT * 16 + 2 * q;
            int m0 = wm * 16 + g;
            unsigned ah[4], al[4];
            ah[0] = *(const unsigned*)&sAh[cur][m0][kb];
            ah[1] = *(const unsigned*)&sAh[cur][m0 + 8][kb];
            ah[2] = *(const unsigned*)&sAh[cur][m0][kb + 8];
            ah[3] = *(const unsigned*)&sAh[cur][m0 + 8][kb + 8];
            al[0] = *(const unsigned*)&sAl[cur][m0][kb];
            al[1] = *(const unsigned*)&sAl[cur][m0 + 8][kb];
            al[2] = *(const unsigned*)&sAl[cur][m0][kb + 8];
            al[3] = *(const unsigned*)&sAl[cur][m0 + 8][kb + 8];
#pragma unroll
            for (int nt = 0; nt < 4; nt++) {
                int n = wn * 32 + nt * 8 + g;
                unsigned bh0 = *(const unsigned*)&sBh[cur][n][kb];
                unsigned bh1 = *(const unsigned*)&sBh[cur][n][kb + 8];
                unsigned bl0 = *(const unsigned*)&sBl[cur][n][kb];
                unsigned bl1 = *(const unsigned*)&sBl[cur][n][kb + 8];
                mma_f16(acc[nt], ah, bh0, bh1);
                mma_f16(acc[nt], ah, bl0, bl1);
                mma_f16(acc[nt], al, bh0, bh1);
            }
        }
        if (havenext) {
            float vf[8] = {v0.x, v0.y, v0.z, v0.w, v1.x, v1.y, v1.z, v1.w};
#pragma unroll
            for (int j = 0; j < 8; j++) {
                __half h = __float2half_rn(vf[j]);
                sAh[nxt][lr][lc + j] = h;
                sAl[nxt][lr][lc + j] = __float2half_rn(vf[j] - __half2float(h));
            }
            *(uint4*)&sBh[nxt][lr][lc] = wbh;
            *(uint4*)&sBl[nxt][lr][lc] = wbl;
        }
        __syncthreads();
    }
#pragma unroll
    for (int nt = 0; nt < 4; nt++) {
        int col0 = bn + wn * 32 + nt * 8 + 2 * q;
        float b0 = bias[col0], b1 = bias[col0 + 1];
        int r0 = bm + wm * 16 + g, r1 = r0 + 8;
        if (r0 < M) {
            C[(size_t)r0 * N + col0]     = fmaxf(acc[nt][0] + b0, 0.f);
            C[(size_t)r0 * N + col0 + 1] = fmaxf(acc[nt][1] + b1, 0.f);
        }
        if (r1 < M) {
            C[(size_t)r1 * N + col0]     = fmaxf(acc[nt][2] + b0, 0.f);
            C[(size_t)r1 * N + col0 + 1] = fmaxf(acc[nt][3] + b1, 0.f);
        }
    }
}

// -------- rcnn cls/box heads + fused stage-2 decode --------
__global__ void k_rheads(const float* __restrict__ wrc, const float* __restrict__ brc,
                         const float* __restrict__ wrb, const float* __restrict__ brb,
                         float* __restrict__ o_log, float* __restrict__ o_del,
                         float* __restrict__ dets) {
    __shared__ float s6[6];
    int p = blockIdx.x;
    int w = threadIdx.x >> 5, lane = threadIdx.x & 31;
    const float* hp = g_h2 + (size_t)p * 512;
    float s = 0.f;
    if (w < 2) {
        for (int k = lane; k < 512; k += 32) s += hp[k] * wrc[k * 2 + w];
    } else {
        int j = w - 2;
        for (int k = lane; k < 512; k += 32) s += hp[k] * wrb[k * 4 + j];
    }
    for (int off = 16; off > 0; off >>= 1) s += __shfl_down_sync(0xffffffffu, s, off);
    if (lane == 0) {
        if (w < 2) {
            float v = s + brc[w];
            o_log[p * 2 + w] = v;
            g_rlogits[p * 2 + w] = v;
            s6[w] = v;
        } else {
            int j = w - 2;
            float v = s + brb[j];
            o_del[p * 4 + j] = v;
            g_rdeltas[p * 4 + j] = v;
            s6[w] = v;
        }
    }
    __syncthreads();
    if (threadIdx.x == 0) {
        float l0 = s6[0], l1 = s6[1];
        float m = fmaxf(l0, l1);
        float e0 = expf(l0 - m), e1 = expf(l1 - m);
        float sc = e1 / (e0 + e1);
        g_dscores[p] = sc;
        float x1 = g_props[p * 4], y1 = g_props[p * 4 + 1];
        float x2 = g_props[p * 4 + 2], y2 = g_props[p * 4 + 3];
        float wd = x2 - x1, h = y2 - y1;
        float cx = x1 + 0.5f * wd, cy = y1 + 0.5f * h;
        float d0 = s6[2], d1 = s6[3], d2 = s6[4], d3 = s6[5];
        float ncx = cx + d0 * wd, ncy = cy + d1 * h;
        float nw = wd * expf(d2), nh = h * expf(d3);
        dets[p * 4]     = fminf(fmaxf(ncx - 0.5f * nw, 0.f), 255.f);
        dets[p * 4 + 1] = fminf(fmaxf(ncy - 0.5f * nh, 0.f), 255.f);
        dets[p * 4 + 2] = fminf(fmaxf(ncx + 0.5f * nw, 0.f), 255.f);
        dets[p * 4 + 3] = fminf(fmaxf(ncy + 0.5f * nh, 0.f), 255.f);
        g_s2[p] = g_valid[p] ? sc : -1.0f;
    }
}

// -------- final dets/scores/keep2 + masks (fused) --------
__global__ void k_final(float* __restrict__ o_fdets, float* __restrict__ o_fsc,
                        float* __restrict__ o_keep, float* __restrict__ o_fmsk) {
    __shared__ float s_kf;
    __shared__ int s_oi;
    int r = blockIdx.x, i = threadIdx.x;
    if (i == 0) {
        int o = g_order2[r];
        int k2 = g_keep2a[r] && g_valid[o];
        float kf = k2 ? 1.f : 0.f;
        float4 d = g_sb2[r];
        o_fdets[r * 4]     = k2 ? d.x : 0.f;
        o_fdets[r * 4 + 1] = k2 ? d.y : 0.f;
        o_fdets[r * 4 + 2] = k2 ? d.z : 0.f;
        o_fdets[r * 4 + 3] = k2 ? d.w : 0.f;
        o_fsc[r] = k2 ? g_dscores[o] : 0.f;
        if (o_keep) o_keep[r] = kf;
        s_kf = kf;
        s_oi = o;
    }
    __syncthreads();
    float v = g_masks[(size_t)s_oi * 196 + i];
    float sgm = 1.f / (1.f + expf(-v));
    o_fmsk[(size_t)r * 196 + i] = sgm * s_kf;
}

// ---------------- host ----------------
extern "C" void kernel_launch(void* const* d_in, const int* in_sizes, int n_in,
                              void* d_out, int out_size) {
    const float* x      = (const float*)d_in[0];
    const float* w_bb   = (const float*)d_in[1];
    const float* b_bb   = (const float*)d_in[2];
    const float* w_rpn  = (const float*)d_in[3];
    const float* b_rpn  = (const float*)d_in[4];
    const float* w_cls  = (const float*)d_in[5];
    const float* b_cls  = (const float*)d_in[6];
    const float* w_box  = (const float*)d_in[7];
    const float* b_box  = (const float*)d_in[8];
    const float* w_fc1  = (const float*)d_in[9];
    const float* b_fc1  = (const float*)d_in[10];
    const float* w_fc2  = (const float*)d_in[11];
    const float* b_fc2  = (const float*)d_in[12];
    const float* w_rcls = (const float*)d_in[13];
    const float* b_rcls = (const float*)d_in[14];
    const float* w_rbox = (const float*)d_in[15];
    const float* b_rbox = (const float*)d_in[16];
    const float* w_m1   = (const float*)d_in[17];
    const float* b_m1   = (const float*)d_in[18];
    const float* w_m2   = (const float*)d_in[19];
    const float* b_m2   = (const float*)d_in[20];
    float* out = (float*)d_out;

    const size_t O_RPNL = 0, O_RPND = 4608, O_PROP = 13824, O_ANCH = 21824;
    const size_t O_RLOG = 31040, O_RDEL = 35040, O_RMSK = 43040;
    const size_t O_FDET = 435040, O_FMSK = 443040, O_FSC = 835040, O_KEEP = 837040;

    float *p_scores, *p_s2, *p_flat, *p_h1, *p_h2, *p_dets, *p_boxes;
    int *p_order, *p_order2, *p_keep1, *p_keep2a;
    unsigned long long *p_mask1, *p_mask2;
    __half *p_bh1, *p_bl1, *p_bh2, *p_bl2;
    cudaGetSymbolAddress((void**)&p_scores, g_scores);
    cudaGetSymbolAddress((void**)&p_order, g_order);
    cudaGetSymbolAddress((void**)&p_s2, g_s2);
    cudaGetSymbolAddress((void**)&p_order2, g_order2);
    cudaGetSymbolAddress((void**)&p_flat, g_flat);
    cudaGetSymbolAddress((void**)&p_h1, g_h1);
    cudaGetSymbolAddress((void**)&p_h2, g_h2);
    cudaGetSymbolAddress((void**)&p_dets, g_dets);
    cudaGetSymbolAddress((void**)&p_boxes, g_boxes);
    cudaGetSymbolAddress((void**)&p_keep1, g_keep1);
    cudaGetSymbolAddress((void**)&p_keep2a, g_keep2a);
    cudaGetSymbolAddress((void**)&p_mask1, g_mask1);
    cudaGetSymbolAddress((void**)&p_mask2, g_mask2);
    cudaGetSymbolAddress((void**)&p_bh1, g_bh1);
    cudaGetSymbolAddress((void**)&p_bl1, g_bl1);
    cudaGetSymbolAddress((void**)&p_bh2, g_bh2);
    cudaGetSymbolAddress((void**)&p_bl2, g_bl2);

    cudaFuncSetAttribute(k_roi, cudaFuncAttributeMaxDynamicSharedMemorySize, SMEM_ROI_BYTES);
    cudaFuncSetAttribute(k_roizero, cudaFuncAttributeMaxDynamicSharedMemorySize, SMEM_ROI_BYTES);

    float4* p_sb1; float* p_sa1; float4* p_sb2; float* p_sa2;
    cudaGetSymbolAddress((void**)&p_sb1, g_sb1);
    cudaGetSymbolAddress((void**)&p_sa1, g_sa1);
    cudaGetSymbolAddress((void**)&p_sb2, g_sb2);
    cudaGetSymbolAddress((void**)&p_sa2, g_sa2);

    k_backbone<<<256, 256>>>(x, w_bb, b_bb);
    k_packwh<<<(9 * 64 * 64 + 255) / 256, 256>>>(w_m1);
    k_packw<<<(64 * 64 * 12 + 255) / 256, 256>>>(w_rpn);
    {
        dim3 tb(32, 8);
        k_packBt<<<dim3(512 / 32, 3136 / 32), tb>>>(w_fc1, p_bh1, p_bl1, 3136, 512);
        k_packBt<<<dim3(512 / 32, 512 / 32), tb>>>(w_fc2, p_bh2, p_bl2, 512, 512);
    }
    k_roizero<<<1, 256, SMEM_ROI_BYTES>>>(b_m1, w_m2, b_m2);
    k_rpnconv<<<256, 512>>>(b_rpn);
    k_heads1<<<18, 128>>>(w_cls, b_cls, w_box, b_box,
                          out + O_RPNL, out + O_RPND, out + O_ANCH);
    k_sort<4096><<<1, 1024>>>(p_scores, NANCH, p_order, p_boxes, p_sb1, p_sa1);
    k_ioumask<NANCH, NW1><<<dim3(NW1, NW1), 64>>>(p_sb1, p_sa1, p_mask1, 0.5f);
    k_nmsreduce<NANCH, NW1><<<1, 32>>>(p_mask1, p_keep1);
    k_select1<<<1, 1024>>>(out + O_PROP);
    k_roi<<<NPROP, 256, SMEM_ROI_BYTES>>>(b_m1, w_m2, b_m2, out + O_RMSK);

    dim3 gfc(8, 32);
    k_gemmh<<<gfc, 256>>>(p_flat, p_bh1, p_bl1, b_fc1, p_h1, NPROP, 512, 3136);
    k_gemmh<<<gfc, 256>>>(p_h1, p_bh2, p_bl2, b_fc2, p_h2, NPROP, 512, 512);
    k_rheads<<<NPROP, 192>>>(w_rcls, b_rcls, w_rbox, b_rbox,
                             out + O_RLOG, out + O_RDEL, p_dets);
    k_sort<2048><<<1, 1024>>>(p_s2, NPROP, p_order2, p_dets, p_sb2, p_sa2);
    k_ioumask<NPROP, NW2><<<dim3(NW2, NW2), 64>>>(p_sb2, p_sa2, p_mask2, 0.3f);
    k_nmsreduce<NPROP, NW2><<<1, 32>>>(p_mask2, p_keep2a);
    float* o_keep = (out_size >= (int)(O_KEEP + NPROP)) ? (out + O_KEEP) : nullptr;
    k_final<<<NPROP, 196>>>(out + O_FDET, out + O_FSC, o_keep, out + O_FMSK);
}

// round 17
// speedup vs baseline: 1.5064x; 1.0191x over previous
#include <cuda_runtime.h>
#include <cuda_fp16.h>
#include <stdint.h>
#include <math.h>

#define NANCH 2304
#define NPROP 2000
#define NW1 36
#define NW2 32

// ---------------- scratch (device globals; no allocation) ----------------
__device__ float g_feat[64 * 256];
__device__ float g_featT[256 * 64];
__device__ float g_featP[64 * 18 * 18];
__device__ float g_hrpn[64 * 256];
__device__ float g_scores[NANCH];
__device__ float g_boxes[NANCH * 4];
__device__ int   g_order[NANCH];
__device__ float g_props[NPROP * 4];
__device__ int   g_valid[NPROP];
__device__ float g_flat[NPROP * 3136];
__device__ float g_h1[NPROP * 512];
__device__ float g_h2[NPROP * 512];
__device__ float g_rlogits[NPROP * 2];
__device__ float g_rdeltas[NPROP * 4];
__device__ float g_dscores[NPROP];
__device__ float g_s2[NPROP];
__device__ int   g_order2[NPROP];
__device__ float g_masks[NPROP * 196];
__device__ float g_dets[NPROP * 4];
__device__ unsigned short g_wh[9 * 64 * 64];     // mask-conv weights fp16 [slab][oc][ic]
__device__ float g_wpack[64 * 64 * 12];          // rpn-conv weights float4-aligned
__device__ float g_flatz[3136];
__device__ float g_maskz[196];
// split-fp16 FC weights, transposed [N][K]
__device__ __half g_bh1[512 * 3136];
__device__ __half g_bl1[512 * 3136];
__device__ __half g_bh2[512 * 512];
__device__ __half g_bl2[512 * 512];
// NMS scratch
__device__ float4 g_sb1[NANCH];
__device__ float  g_sa1[NANCH];
__device__ unsigned long long g_mask1[(size_t)NANCH * NW1];
__device__ int    g_keep1[NANCH];
__device__ float4 g_sb2[NPROP];
__device__ float  g_sa2[NPROP];
__device__ unsigned long long g_mask2[(size_t)NPROP * NW2];
__device__ int    g_keep2a[NPROP];

__device__ __forceinline__ void mma_f16(float* c, const unsigned* a,
                                        unsigned b0, unsigned b1) {
    asm volatile(
        "mma.sync.aligned.m16n8k16.row.col.f32.f16.f16.f32 "
        "{%0,%1,%2,%3},{%4,%5,%6,%7},{%8,%9},{%0,%1,%2,%3};"
        : "+f"(c[0]), "+f"(c[1]), "+f"(c[2]), "+f"(c[3])
        : "r"(a[0]), "r"(a[1]), "r"(a[2]), "r"(a[3]), "r"(b0), "r"(b1));
}

// ---------------- backbone ----------------
__global__ void k_backbone(const float* __restrict__ x, const float* __restrict__ w,
                           const float* __restrict__ b) {
    __shared__ float patch[768];
    __shared__ float part[256];
    int pos = blockIdx.x;
    int h = pos >> 4, wq = pos & 15;
    int tid = threadIdx.x;
    for (int k = tid; k < 768; k += 256) {
        int ic = k >> 8, r = k & 255, iy = r >> 4, ix = r & 15;
        patch[k] = x[ic * 65536 + (h * 16 + iy) * 256 + (wq * 16 + ix)];
    }
    __syncthreads();
    int oc = tid & 63, ch = tid >> 6;
    const float* wp = w + oc * 768 + ch * 192;
    const float* pp = patch + ch * 192;
    float a0 = 0.f, a1 = 0.f;
#pragma unroll 8
    for (int k = 0; k < 192; k += 2) { a0 += pp[k] * wp[k]; a1 += pp[k + 1] * wp[k + 1]; }
    part[tid] = a0 + a1;
    __syncthreads();
    if (tid < 64) {
        float s = b[tid] + part[tid] + part[tid + 64] + part[tid + 128] + part[tid + 192];
        float v = fmaxf(s, 0.f);
        g_feat[tid * 256 + pos] = v;
        g_featT[pos * 64 + tid] = v;
        g_featP[tid * 324 + (h + 1) * 18 + (wq + 1)] = v;
    }
}

// -------- pack rpn weights [oc][ic][9] -> [oc][ic][12] (float4-aligned) ----
__global__ void k_packw(const float* __restrict__ w) {
    int i = blockIdx.x * blockDim.x + threadIdx.x;
    if (i >= 64 * 64 * 12) return;
    int pair = i / 12, q = i % 12;
    g_wpack[i] = (q < 9) ? w[pair * 9 + q] : 0.f;
}

// ---------------- rpn conv 3x3 SAME, relu (8-way splitK, 512 thr) ----------------
__global__ void k_rpnconv(const float* __restrict__ b) {
    __shared__ float s_f[576];
    __shared__ float part[512];
    int pos = blockIdx.x;
    int y = pos >> 4, xq = pos & 15;
    int tid = threadIdx.x;
    for (int k = tid; k < 576; k += 512) {
        int ic = k / 9, r = k % 9, ky = r / 3, kx = r % 3;
        s_f[k] = g_featP[ic * 324 + (y + ky) * 18 + (xq + kx)];
    }
    __syncthreads();
    int oc = tid & 63, ch = tid >> 6;
    const float4* wp4 = (const float4*)g_wpack;
    float acc0 = 0.f, acc1 = 0.f;
    for (int icl = 0; icl < 8; icl += 2) {
        int ic = ch * 8 + icl;
        float4 A0 = wp4[(oc * 64 + ic) * 3], A1 = wp4[(oc * 64 + ic) * 3 + 1],
               A2 = wp4[(oc * 64 + ic) * 3 + 2];
        float4 B0 = wp4[(oc * 64 + ic + 1) * 3], B1 = wp4[(oc * 64 + ic + 1) * 3 + 1],
               B2 = wp4[(oc * 64 + ic + 1) * 3 + 2];
        float wAr[9] = {A0.x, A0.y, A0.z, A0.w, A1.x, A1.y, A1.z, A1.w, A2.x};
        float wBr[9] = {B0.x, B0.y, B0.z, B0.w, B1.x, B1.y, B1.z, B1.w, B2.x};
        const float* f0 = s_f + ic * 9;
#pragma unroll
        for (int k = 0; k < 9; k++) {
            acc0 += f0[k] * wAr[k];
            acc1 += f0[9 + k] * wBr[k];
        }
    }
    part[tid] = acc0 + acc1;
    __syncthreads();
    if (tid < 64) {
        float s = b[tid];
#pragma unroll
        for (int j = 0; j < 8; j++) s += part[tid + 64 * j];
        g_hrpn[tid * 256 + pos] = fmaxf(s, 0.f);
    }
}

// -------- rpn heads (1x1), anchors, softmax score, decode, clip --------
__global__ void k_heads1(const float* __restrict__ wc, const float* __restrict__ bc,
                         const float* __restrict__ wb, const float* __restrict__ bb,
                         float* __restrict__ o_logits, float* __restrict__ o_deltas,
                         float* __restrict__ o_anch) {
    int i = blockIdx.x * blockDim.x + threadIdx.x;
    if (i >= NANCH) return;
    int cell = i / 9, a = i % 9;
    float l0 = bc[a * 2], l1 = bc[a * 2 + 1];
    float d0 = bb[a * 4], d1 = bb[a * 4 + 1], d2 = bb[a * 4 + 2], d3 = bb[a * 4 + 3];
    for (int ic = 0; ic < 64; ic++) {
        float f = g_hrpn[ic * 256 + cell];
        l0 += f * wc[(a * 2) * 64 + ic];
        l1 += f * wc[(a * 2 + 1) * 64 + ic];
        d0 += f * wb[(a * 4) * 64 + ic];
        d1 += f * wb[(a * 4 + 1) * 64 + ic];
        d2 += f * wb[(a * 4 + 2) * 64 + ic];
        d3 += f * wb[(a * 4 + 3) * 64 + ic];
    }
    o_logits[i * 2] = l0; o_logits[i * 2 + 1] = l1;
    o_deltas[i * 4] = d0; o_deltas[i * 4 + 1] = d1;
    o_deltas[i * 4 + 2] = d2; o_deltas[i * 4 + 3] = d3;
    float m = fmaxf(l0, l1);
    float e0 = expf(l0 - m), e1 = expf(l1 - m);
    g_scores[i] = e1 / (e0 + e1);

    const float S[3] = {32.f, 64.f, 128.f};
    const float R[3] = {0.5f, 1.f, 2.f};
    int h = cell >> 4, wq = cell & 15;
    float s = S[a / 3], r = R[a % 3];
    float ws = s * sqrtf(r), hs = s / sqrtf(r);
    float cx = (wq + 0.5f) * 16.f, cy = (h + 0.5f) * 16.f;
    float ax1 = cx - ws * 0.5f, ay1 = cy - hs * 0.5f;
    float ax2 = cx + ws * 0.5f, ay2 = cy + hs * 0.5f;
    o_anch[i * 4] = ax1; o_anch[i * 4 + 1] = ay1;
    o_anch[i * 4 + 2] = ax2; o_anch[i * 4 + 3] = ay2;

    float aw = ax2 - ax1, ah = ay2 - ay1;
    float acx = ax1 + 0.5f * aw, acy = ay1 + 0.5f * ah;
    float ncx = acx + d0 * aw, ncy = acy + d1 * ah;
    float nw = aw * expf(d2), nh = ah * expf(d3);
    g_boxes[i * 4]     = fminf(fmaxf(ncx - 0.5f * nw, 0.f), 255.f);
    g_boxes[i * 4 + 1] = fminf(fmaxf(ncy - 0.5f * nh, 0.f), 255.f);
    g_boxes[i * 4 + 2] = fminf(fmaxf(ncx + 0.5f * nw, 0.f), 255.f);
    g_boxes[i * 4 + 3] = fminf(fmaxf(ncy + 0.5f * nh, 0.f), 255.f);
}

// -------- pack mask-conv weights fp16 [slab][oc][ic] ----
__global__ void k_packwh(const float* __restrict__ w) {
    int i = blockIdx.x * blockDim.x + threadIdx.x;
    if (i >= 9 * 64 * 64) return;
    int slab = i >> 12, r = i & 4095, oc = r >> 6, ic = r & 63;
    g_wh[i] = __half_as_ushort(__float2half_rn(w[oc * 576 + ic * 9 + slab]));
}

// -------- tiled transpose pack: w[K][N] -> Bh/Bl [N][K] split-fp16 ----
__global__ void k_packBt(const float* __restrict__ w, __half* __restrict__ Bh,
                         __half* __restrict__ Bl, int K, int N) {
    __shared__ float tile[32][33];
    int kb = blockIdx.y * 32, nb = blockIdx.x * 32;
    int tx = threadIdx.x, ty = threadIdx.y;   // 32 x 8
#pragma unroll
    for (int i = 0; i < 32; i += 8) {
        int k = kb + ty + i, n = nb + tx;
        tile[ty + i][tx] = (k < K && n < N) ? w[(size_t)k * N + n] : 0.f;
    }
    __syncthreads();
#pragma unroll
    for (int i = 0; i < 32; i += 8) {
        int n = nb + ty + i, k = kb + tx;
        if (n < N && k < K) {
            float x = tile[tx][ty + i];
            __half h = __float2half_rn(x);
            Bh[(size_t)n * K + k] = h;
            Bl[(size_t)n * K + k] = __float2half_rn(x - __half2float(h));
        }
    }
}

// -------- exact O(N^2) rank sort: desc value, stable idx; fused box gather --------
// key construction identical to prior bitonic sort => identical permutation
template <int N>
__global__ void k_ranksort(const float* __restrict__ sc, int* __restrict__ ord,
                           const float* __restrict__ boxes, float4* __restrict__ sb,
                           float* __restrict__ sa) {
    __shared__ unsigned long long keys[N];
    int tid = threadIdx.x;
    int i = blockIdx.x * 256 + tid;
    for (int k = tid; k < N; k += 256) {
        unsigned u = __float_as_uint(sc[k]);
        unsigned o = (u & 0x80000000u) ? ~u : (u | 0x80000000u);
        keys[k] = ((unsigned long long)(~o) << 32) | (unsigned)k;
    }
    __syncthreads();
    if (i >= N) return;
    unsigned long long mykey = keys[i];
    int rank = 0;
#pragma unroll 4
    for (int k = 0; k < N; k++)
        rank += (keys[k] < mykey) ? 1 : 0;
    ord[rank] = i;
    float4 b = *(const float4*)&boxes[i * 4];
    sb[rank] = b;
    sa[rank] = fmaxf(b.z - b.x, 0.f) * fmaxf(b.w - b.y, 0.f);
}

// -------- IoU bitmask matrix --------
template <int N, int NW>
__global__ void k_ioumask(const float4* __restrict__ sb, const float* __restrict__ sa,
                          unsigned long long* __restrict__ mask, float thr) {
    __shared__ float4 cbx[64];
    __shared__ float car[64];
    int rb = blockIdx.y, cb = blockIdx.x;
    int t = threadIdx.x;
    int j0 = cb * 64;
    if (j0 + t < N) { cbx[t] = sb[j0 + t]; car[t] = sa[j0 + t]; }
    __syncthreads();
    int i = rb * 64 + t;
    if (i >= N) return;
    float4 bi = sb[i];
    float ai = sa[i];
    unsigned long long m = 0;
    int jmax = min(64, N - j0);
    for (int jj = 0; jj < jmax; jj++) {
        int j = j0 + jj;
        if (j <= i) continue;
        float xx1 = fmaxf(bi.x, cbx[jj].x), yy1 = fmaxf(bi.y, cbx[jj].y);
        float xx2 = fminf(bi.z, cbx[jj].z), yy2 = fminf(bi.w, cbx[jj].w);
        float inter = fmaxf(xx2 - xx1, 0.f) * fmaxf(yy2 - yy1, 0.f);
        float iou = inter / (ai + car[jj] - inter + 1e-8f);
        if (iou > thr) m |= 1ULL << jj;
    }
    mask[(size_t)i * NW + cb] = m;
}

// -------- chunked exact greedy reduce --------
template <int N, int NW>
__global__ void k_nmsreduce(const unsigned long long* __restrict__ mask,
                            int* __restrict__ keep) {
    __shared__ unsigned long long s_blk[64];
    int lane = threadIdx.x;
    unsigned long long remv0 = 0ULL, remv1 = 0ULL;
    const int NC = (N + 63) / 64;
    for (int cb = 0; cb < NC; cb++) {
        int j0 = cb * 64;
        int jmax = min(64, N - j0);
        for (int t = lane; t < jmax; t += 32)
            s_blk[t] = mask[(size_t)(j0 + t) * NW + cb];
        __syncwarp();
        int owner = cb & 31;
        unsigned long long r = __shfl_sync(0xffffffffu, (cb < 32) ? remv0 : remv1, owner);
        unsigned long long kept = 0ULL;
        if (lane == 0) {
#pragma unroll 4
            for (int jj = 0; jj < jmax; jj++) {
                if (!((r >> jj) & 1ULL)) {
                    kept |= 1ULL << jj;
                    r |= s_blk[jj];
                }
            }
        }
        kept = __shfl_sync(0xffffffffu, kept, 0);
        r = __shfl_sync(0xffffffffu, r, 0);
        if (lane == owner) { if (cb < 32) remv0 = r; else remv1 = r; }
        for (int t = lane; t < jmax; t += 32)
            keep[j0 + t] = (int)((kept >> t) & 1ULL);
        int w1 = lane, w2 = lane + 32;
        bool u1 = (w1 > cb) && (w1 < NW), u2 = (w2 > cb) && (w2 < NW);
        for (int jj = 0; jj < jmax; jj++) {
            if ((kept >> jj) & 1ULL) {
                const unsigned long long* row = mask + (size_t)(j0 + jj) * NW;
                if (u1) remv0 |= row[w1];
                if (u2) remv1 |= row[w2];
            }
        }
        __syncwarp();
    }
}

// -------- stable kept-first selection --------
__global__ void k_select1(float* __restrict__ o_props) {
    __shared__ int s_src[NPROP];
    int tid = threadIdx.x;
    if (tid < 32) {
        const int CH = NANCH / 32;
        int beg = tid * CH, end = beg + CH;
        int cnt = 0;
        for (int i = beg; i < end; i++) cnt += g_keep1[i];
        int xsc = cnt;
        for (int off = 1; off < 32; off <<= 1) {
            int v = __shfl_up_sync(0xffffffffu, xsc, off);
            if (tid >= off) xsc += v;
        }
        int excl = xsc - cnt;
        int total = __shfl_sync(0xffffffffu, xsc, 31);
        int kpos = excl;
        int npos = total + (beg - excl);
        for (int i = beg; i < end; i++) {
            int pos = g_keep1[i] ? kpos++ : npos++;
            if (pos < NPROP) s_src[pos] = i;
        }
    }
    __syncthreads();
    for (int p = tid; p < NPROP; p += 1024) {
        int i = s_src[p];
        int v = g_keep1[i];
        float4 bb = g_sb1[i];
        float px1 = v ? bb.x : 0.f, py1 = v ? bb.y : 0.f;
        float px2 = v ? bb.z : 0.f, py2 = v ? bb.w : 0.f;
        g_props[p * 4] = px1; g_props[p * 4 + 1] = py1;
        g_props[p * 4 + 2] = px2; g_props[p * 4 + 3] = py2;
        o_props[p * 4] = px1; o_props[p * 4 + 1] = py1;
        o_props[p * 4 + 2] = px2; o_props[p * 4 + 3] = py2;
        g_valid[p] = v;
    }
}

// ===================== ROI body: fp16 MMA, double-buffered weight slabs =====
#define CROPH_H (16 * 16 * 72)
#define WSLAB_H (64 * 72)
#define SMEM_ROI_BYTES (CROPH_H * 2 + 2 * WSLAB_H * 2 + (64 + 64 + 28) * 4 + 56 * 4 + 16)

__device__ __forceinline__ void roi_body(
    int tid, float bx1, float by1, float bx2, float by2,
    const float* __restrict__ bm1, const float* __restrict__ wm2,
    const float* __restrict__ bm2,
    float* __restrict__ flat_out, float* __restrict__ maskA, float* __restrict__ maskB,
    __half* smem)
{
    __half* s_ch = smem;
    __half* s_wh = smem + CROPH_H;
    float* s_w2 = (float*)(smem + CROPH_H + 2 * WSLAB_H);
    float* s_b1 = s_w2 + 64;
    float* s_wy = s_b1 + 64;
    float* s_wx = s_wy + 14;
    int* s_y0 = (int*)(s_wx + 14);
    int* s_y1 = s_y0 + 14;
    int* s_x0 = s_y1 + 14;
    int* s_x1 = s_x0 + 14;

    int lane = tid & 31, wrp = tid >> 5;

    if (tid < 28) {
        int t = tid % 14;
        float tt = (float)t / 13.0f;
        if (tid < 14) {
            float y1n = by1 / 255.0f, y2n = by2 / 255.0f;
            float fy = (y1n + (y2n - y1n) * tt) * 15.0f;
            float y0f = fminf(fmaxf(floorf(fy), 0.f), 15.f);
            int y0 = (int)y0f;
            s_y0[t] = y0; s_y1[t] = min(y0 + 1, 15); s_wy[t] = fy - y0f;
        } else {
            float x1n = bx1 / 255.0f, x2n = bx2 / 255.0f;
            float fx = (x1n + (x2n - x1n) * tt) * 15.0f;
            float x0f = fminf(fmaxf(floorf(fx), 0.f), 15.f);
            int x0 = (int)x0f;
            s_x0[t] = x0; s_x1[t] = min(x0 + 1, 15); s_wx[t] = fx - x0f;
        }
    }
    if (tid >= 32 && tid < 96) {
        int c = tid - 32;
        s_w2[c] = wm2[c];
        s_b1[c] = bm1[c];
    }
    for (int idx = tid; idx < CROPH_H / 2; idx += 256)
        ((unsigned*)s_ch)[idx] = 0u;
    __syncthreads();

    const float4* ft4 = (const float4*)g_featT;
    for (int task = tid; task < 784; task += 256) {
        int cell = task >> 4, c4 = task & 15;
        int py = cell / 7, px = cell - py * 7;
        float4 v[2][2];
#pragma unroll
        for (int dy = 0; dy < 2; dy++)
#pragma unroll
            for (int dx = 0; dx < 2; dx++) {
                int ty = 2 * py + dy, tx = 2 * px + dx;
                int y0 = s_y0[ty], y1 = s_y1[ty], x0 = s_x0[tx], x1 = s_x1[tx];
                float wy = s_wy[ty], wx = s_wx[tx];
                float4 f00 = ft4[(y0 * 16 + x0) * 16 + c4];
                float4 f01 = ft4[(y0 * 16 + x1) * 16 + c4];
                float4 f10 = ft4[(y1 * 16 + x0) * 16 + c4];
                float4 f11 = ft4[(y1 * 16 + x1) * 16 + c4];
                float4 r;
                { float top = f00.x * (1.f - wx) + f01.x * wx;
                  float bot = f10.x * (1.f - wx) + f11.x * wx;
                  r.x = top * (1.f - wy) + bot * wy; }
                { float top = f00.y * (1.f - wx) + f01.y * wx;
                  float bot = f10.y * (1.f - wx) + f11.y * wx;
                  r.y = top * (1.f - wy) + bot * wy; }
                { float top = f00.z * (1.f - wx) + f01.z * wx;
                  float bot = f10.z * (1.f - wx) + f11.z * wx;
                  r.z = top * (1.f - wy) + bot * wy; }
                { float top = f00.w * (1.f - wx) + f01.w * wx;
                  float bot = f10.w * (1.f - wx) + f11.w * wx;
                  r.w = top * (1.f - wy) + bot * wy; }
                v[dy][dx] = r;
                __half2* dst = (__half2*)&s_ch[((ty + 1) * 16 + (tx + 1)) * 72 + c4 * 4];
                dst[0] = __floats2half2_rn(r.x, r.y);
                dst[1] = __floats2half2_rn(r.z, r.w);
            }
        flat_out[(c4 * 4 + 0) * 49 + cell] =
            fmaxf(fmaxf(v[0][0].x, v[0][1].x), fmaxf(v[1][0].x, v[1][1].x));
        flat_out[(c4 * 4 + 1) * 49 + cell] =
            fmaxf(fmaxf(v[0][0].y, v[0][1].y), fmaxf(v[1][0].y, v[1][1].y));
        flat_out[(c4 * 4 + 2) * 49 + cell] =
            fmaxf(fmaxf(v[0][0].z, v[0][1].z), fmaxf(v[1][0].z, v[1][1].z));
        flat_out[(c4 * 4 + 3) * 49 + cell] =
            fmaxf(fmaxf(v[0][0].w, v[0][1].w), fmaxf(v[1][0].w, v[1][1].w));
    }

    int g = lane >> 2, q = lane & 3;
    int pb[2][2];
#pragma unroll
    for (int mt = 0; mt < 2; mt++)
#pragma unroll
        for (int hh = 0; hh < 2; hh++) {
            int p = wrp * 32 + mt * 16 + g + hh * 8;
            if (p < 196) {
                int y = p / 14, xx = p % 14;
                pb[mt][hh] = (y * 16 + xx) * 72;
            } else pb[mt][hh] = 0;
        }

    float c[2][8][4];
#pragma unroll
    for (int mt = 0; mt < 2; mt++)
#pragma unroll
        for (int nt = 0; nt < 8; nt++)
#pragma unroll
            for (int j = 0; j < 4; j++) c[mt][nt][j] = 0.f;

    const unsigned* gwu = (const unsigned*)g_wh;
    int sidx[9], gofs[9];
#pragma unroll
    for (int j = 0; j < 9; j++) {
        int f = tid + j * 256;
        int oc = f / 36, icu = f - oc * 36;
        sidx[j] = oc * 36 + icu;
        gofs[j] = (icu < 32) ? (oc * 32 + icu) : -1;
    }
    unsigned wreg[9];
#pragma unroll
    for (int j = 0; j < 9; j++)
        wreg[j] = (gofs[j] >= 0) ? gwu[gofs[j]] : 0u;
    {
        unsigned* buf0 = (unsigned*)s_wh;
#pragma unroll
        for (int j = 0; j < 9; j++) buf0[sidx[j]] = wreg[j];
    }
    __syncthreads();

    for (int slab = 0; slab < 9; slab++) {
        bool havenext = (slab + 1 < 9);
        if (havenext) {
            const unsigned* gsl = gwu + (slab + 1) * 2048;
#pragma unroll
            for (int j = 0; j < 9; j++)
                wreg[j] = (gofs[j] >= 0) ? gsl[gofs[j]] : 0u;
        }
        const __half* wbuf = s_wh + (slab & 1) * WSLAB_H;
        int ky = slab / 3, kx = slab % 3;
        int off = (ky * 16 + kx) * 72;
#pragma unroll
        for (int kT = 0; kT < 4; kT++) {
            int ab = off + kT * 16 + 2 * q;
            unsigned a[2][4];
#pragma unroll
            for (int mt = 0; mt < 2; mt++) {
                a[mt][0] = *(const unsigned*)&s_ch[pb[mt][0] + ab];
                a[mt][1] = *(const unsigned*)&s_ch[pb[mt][1] + ab];
                a[mt][2] = *(const unsigned*)&s_ch[pb[mt][0] + ab + 8];
                a[mt][3] = *(const unsigned*)&s_ch[pb[mt][1] + ab + 8];
            }
            int bbase = kT * 16 + 2 * q;
#pragma unroll
            for (int nt = 0; nt < 8; nt++) {
                int oc = nt * 8 + g;
                unsigned b0 = *(const unsigned*)&wbuf[oc * 72 + bbase];
                unsigned b1 = *(const unsigned*)&wbuf[oc * 72 + bbase + 8];
                mma_f16(c[0][nt], a[0], b0, b1);
                mma_f16(c[1][nt], a[1], b0, b1);
            }
        }
        if (havenext) {
            unsigned* nbuf = (unsigned*)(s_wh + ((slab + 1) & 1) * WSLAB_H);
#pragma unroll
            for (int j = 0; j < 9; j++) nbuf[sidx[j]] = wreg[j];
        }
        __syncthreads();
    }

    float part[2][2] = {{0.f, 0.f}, {0.f, 0.f}};
#pragma unroll
    for (int nt = 0; nt < 8; nt++) {
        int col0 = nt * 8 + q * 2, col1 = col0 + 1;
        float bA = s_b1[col0], bB = s_b1[col1];
        float w20 = s_w2[col0], w21 = s_w2[col1];
#pragma unroll
        for (int mt = 0; mt < 2; mt++) {
            part[mt][0] += fmaxf(c[mt][nt][0] + bA, 0.f) * w20
                         + fmaxf(c[mt][nt][1] + bB, 0.f) * w21;
            part[mt][1] += fmaxf(c[mt][nt][2] + bA, 0.f) * w20
                         + fmaxf(c[mt][nt][3] + bB, 0.f) * w21;
        }
    }
    float b2 = bm2[0];
#pragma unroll
    for (int mt = 0; mt < 2; mt++)
#pragma unroll
        for (int hh = 0; hh < 2; hh++) {
            float v = part[mt][hh];
            v += __shfl_xor_sync(0xffffffffu, v, 1);
            v += __shfl_xor_sync(0xffffffffu, v, 2);
            int p = wrp * 32 + mt * 16 + g + hh * 8;
            if (q == 0 && p < 196) {
                float logit = b2 + v;
                maskA[p] = logit;
                maskB[p] = logit;
            }
        }
}

__global__ void __launch_bounds__(256, 2)
k_roizero(const float* __restrict__ bm1, const float* __restrict__ wm2,
          const float* __restrict__ bm2) {
    extern __shared__ __half smem_h[];
    roi_body(threadIdx.x, 0.f, 0.f, 0.f, 0.f, bm1, wm2, bm2,
             g_flatz, g_maskz, g_maskz, smem_h);
}

__global__ void __launch_bounds__(256, 2)
k_roi(const float* __restrict__ bm1, const float* __restrict__ wm2,
      const float* __restrict__ bm2, float* __restrict__ omask) {
    extern __shared__ __half smem_h[];
    int p = blockIdx.x, tid = threadIdx.x;
    if (!g_valid[p]) {
        float* fo = g_flat + (size_t)p * 3136;
        for (int idx = tid; idx < 784; idx += 256)
            ((float4*)fo)[idx] = ((const float4*)g_flatz)[idx];
        for (int pos = tid; pos < 196; pos += 256) {
            float v = g_maskz[pos];
            omask[(size_t)p * 196 + pos] = v;
            g_masks[(size_t)p * 196 + pos] = v;
        }
        return;
    }
    roi_body(tid, g_props[p * 4], g_props[p * 4 + 1], g_props[p * 4 + 2], g_props[p * 4 + 3],
             bm1, wm2, bm2,
             g_flat + (size_t)p * 3136, omask + (size_t)p * 196,
             g_masks + (size_t)p * 196, smem_h);
}

// ===== split-fp16 GEMM (fp32 A, on-the-fly split), double-buffered =====
__global__ void __launch_bounds__(256, 2)
k_gemmh(const float* __restrict__ A, const __half* __restrict__ Bh,
        const __half* __restrict__ Bl, const float* __restrict__ bias,
        float* __restrict__ C, int M, int N, int K) {
    __shared__ __half sAh[2][64][40], sAl[2][64][40], sBh[2][64][40], sBl[2][64][40];
    int tid = threadIdx.x;
    int lane = tid & 31, wrp = tid >> 5;
    int wm = wrp >> 1, wn = wrp & 1;
    int g = lane >> 2, q = lane & 3;
    int bm = blockIdx.y * 64, bn = blockIdx.x * 64;

    float acc[4][4];
#pragma unroll
    for (int nt = 0; nt < 4; nt++)
#pragma unroll
        for (int j = 0; j < 4; j++) acc[nt][j] = 0.f;

    int lr = tid >> 2, lc = (tid & 3) * 8;
    int arow = bm + lr;
    bool aok = arow < M;
    const __half* bhrow = Bh + (size_t)(bn + lr) * K;
    const __half* blrow = Bl + (size_t)(bn + lr) * K;
    const int nk = K / 32;

    {
        float4 v0 = make_float4(0.f, 0.f, 0.f, 0.f), v1 = v0;
        if (aok) {
            v0 = *(const float4*)&A[(size_t)arow * K + lc];
            v1 = *(const float4*)&A[(size_t)arow * K + lc + 4];
        }
        float vf[8] = {v0.x, v0.y, v0.z, v0.w, v1.x, v1.y, v1.z, v1.w};
#pragma unroll
        for (int j = 0; j < 8; j++) {
            __half h = __float2half_rn(vf[j]);
            sAh[0][lr][lc + j] = h;
            sAl[0][lr][lc + j] = __float2half_rn(vf[j] - __half2float(h));
        }
        *(uint4*)&sBh[0][lr][lc] = *(const uint4*)&bhrow[lc];
        *(uint4*)&sBl[0][lr][lc] = *(const uint4*)&blrow[lc];
    }
    __syncthreads();

    for (int t = 0; t < nk; t++) {
        int cur = t & 1, nxt = cur ^ 1;
        float4 v0, v1;
        uint4 wbh, wbl;
        bool havenext = (t + 1 < nk);
        if (havenext) {
            int k0 = (t + 1) * 32;
            v0 = make_float4(0.f, 0.f, 0.f, 0.f); v1 = v0;
            if (aok) {
                v0 = *(const float4*)&A[(size_t)arow * K + k0 + lc];
                v1 = *(const float4*)&A[(size_t)arow * K + k0 + lc + 4];
            }
            wbh = *(const uint4*)&bhrow[k0 + lc];
            wbl = *(const uint4*)&blrow[k0 + lc];
        }
#pragma unroll
        for (int kT = 0; kT < 2; kT++) {
            int kb = kT * 16 + 2 * q;
            int m0 = wm * 16 + g;
            unsigned ah[4], al[4];
            ah[0] = *(const unsigned*)&sAh[cur][m0][kb];
            ah[1] = *(const unsigned*)&sAh[cur][m0 + 8][kb];
            ah[2] = *(const unsigned*)&sAh[cur][m0][kb + 8];
            ah[3] = *(const unsigned*)&sAh[cur][m0 + 8][kb + 8];
            al[0] = *(const unsigned*)&sAl[cur][m0][kb];
            al[1] = *(const unsigned*)&sAl[cur][m0 + 8][kb];
            al[2] = *(const unsigned*)&sAl[cur][m0][kb + 8];
            al[3] = *(const unsigned*)&sAl[cur][m0 + 8][kb + 8];
#pragma unroll
            for (int nt = 0; nt < 4; nt++) {
                int n = wn * 32 + nt * 8 + g;
                unsigned bh0 = *(const unsigned*)&sBh[cur][n][kb];
                unsigned bh1 = *(const unsigned*)&sBh[cur][n][kb + 8];
                unsigned bl0 = *(const unsigned*)&sBl[cur][n][kb];
                unsigned bl1 = *(const unsigned*)&sBl[cur][n][kb + 8];
                mma_f16(acc[nt], ah, bh0, bh1);
                mma_f16(acc[nt], ah, bl0, bl1);
                mma_f16(acc[nt], al, bh0, bh1);
            }
        }
        if (havenext) {
            float vf[8] = {v0.x, v0.y, v0.z, v0.w, v1.x, v1.y, v1.z, v1.w};
#pragma unroll
            for (int j = 0; j < 8; j++) {
                __half h = __float2half_rn(vf[j]);
                sAh[nxt][lr][lc + j] = h;
                sAl[nxt][lr][lc + j] = __float2half_rn(vf[j] - __half2float(h));
            }
            *(uint4*)&sBh[nxt][lr][lc] = wbh;
            *(uint4*)&sBl[nxt][lr][lc] = wbl;
        }
        __syncthreads();
    }
#pragma unroll
    for (int nt = 0; nt < 4; nt++) {
        int col0 = bn + wn * 32 + nt * 8 + 2 * q;
        float b0 = bias[col0], b1 = bias[col0 + 1];
        int r0 = bm + wm * 16 + g, r1 = r0 + 8;
        if (r0 < M) {
            C[(size_t)r0 * N + col0]     = fmaxf(acc[nt][0] + b0, 0.f);
            C[(size_t)r0 * N + col0 + 1] = fmaxf(acc[nt][1] + b1, 0.f);
        }
        if (r1 < M) {
            C[(size_t)r1 * N + col0]     = fmaxf(acc[nt][2] + b0, 0.f);
            C[(size_t)r1 * N + col0 + 1] = fmaxf(acc[nt][3] + b1, 0.f);
        }
    }
}

// -------- rcnn cls/box heads + fused stage-2 decode --------
__global__ void k_rheads(const float* __restrict__ wrc, const float* __restrict__ brc,
                         const float* __restrict__ wrb, const float* __restrict__ brb,
                         float* __restrict__ o_log, float* __restrict__ o_del,
                         float* __restrict__ dets) {
    __shared__ float s6[6];
    int p = blockIdx.x;
    int w = threadIdx.x >> 5, lane = threadIdx.x & 31;
    const float* hp = g_h2 + (size_t)p * 512;
    float s = 0.f;
    if (w < 2) {
        for (int k = lane; k < 512; k += 32) s += hp[k] * wrc[k * 2 + w];
    } else {
        int j = w - 2;
        for (int k = lane; k < 512; k += 32) s += hp[k] * wrb[k * 4 + j];
    }
    for (int off = 16; off > 0; off >>= 1) s += __shfl_down_sync(0xffffffffu, s, off);
    if (lane == 0) {
        if (w < 2) {
            float v = s + brc[w];
            o_log[p * 2 + w] = v;
            g_rlogits[p * 2 + w] = v;
            s6[w] = v;
        } else {
            int j = w - 2;
            float v = s + brb[j];
            o_del[p * 4 + j] = v;
            g_rdeltas[p * 4 + j] = v;
            s6[w] = v;
        }
    }
    __syncthreads();
    if (threadIdx.x == 0) {
        float l0 = s6[0], l1 = s6[1];
        float m = fmaxf(l0, l1);
        float e0 = expf(l0 - m), e1 = expf(l1 - m);
        float sc = e1 / (e0 + e1);
        g_dscores[p] = sc;
        float x1 = g_props[p * 4], y1 = g_props[p * 4 + 1];
        float x2 = g_props[p * 4 + 2], y2 = g_props[p * 4 + 3];
        float wd = x2 - x1, h = y2 - y1;
        float cx = x1 + 0.5f * wd, cy = y1 + 0.5f * h;
        float d0 = s6[2], d1 = s6[3], d2 = s6[4], d3 = s6[5];
        float ncx = cx + d0 * wd, ncy = cy + d1 * h;
        float nw = wd * expf(d2), nh = h * expf(d3);
        dets[p * 4]     = fminf(fmaxf(ncx - 0.5f * nw, 0.f), 255.f);
        dets[p * 4 + 1] = fminf(fmaxf(ncy - 0.5f * nh, 0.f), 255.f);
        dets[p * 4 + 2] = fminf(fmaxf(ncx + 0.5f * nw, 0.f), 255.f);
        dets[p * 4 + 3] = fminf(fmaxf(ncy + 0.5f * nh, 0.f), 255.f);
        g_s2[p] = g_valid[p] ? sc : -1.0f;
    }
}

// -------- final dets/scores/keep2 + masks (fused) --------
__global__ void k_final(float* __restrict__ o_fdets, float* __restrict__ o_fsc,
                        float* __restrict__ o_keep, float* __restrict__ o_fmsk) {
    __shared__ float s_kf;
    __shared__ int s_oi;
    int r = blockIdx.x, i = threadIdx.x;
    if (i == 0) {
        int o = g_order2[r];
        int k2 = g_keep2a[r] && g_valid[o];
        float kf = k2 ? 1.f : 0.f;
        float4 d = g_sb2[r];
        o_fdets[r * 4]     = k2 ? d.x : 0.f;
        o_fdets[r * 4 + 1] = k2 ? d.y : 0.f;
        o_fdets[r * 4 + 2] = k2 ? d.z : 0.f;
        o_fdets[r * 4 + 3] = k2 ? d.w : 0.f;
        o_fsc[r] = k2 ? g_dscores[o] : 0.f;
        if (o_keep) o_keep[r] = kf;
        s_kf = kf;
        s_oi = o;
    }
    __syncthreads();
    float v = g_masks[(size_t)s_oi * 196 + i];
    float sgm = 1.f / (1.f + expf(-v));
    o_fmsk[(size_t)r * 196 + i] = sgm * s_kf;
}

// ---------------- host ----------------
extern "C" void kernel_launch(void* const* d_in, const int* in_sizes, int n_in,
                              void* d_out, int out_size) {
    const float* x      = (const float*)d_in[0];
    const float* w_bb   = (const float*)d_in[1];
    const float* b_bb   = (const float*)d_in[2];
    const float* w_rpn  = (const float*)d_in[3];
    const float* b_rpn  = (const float*)d_in[4];
    const float* w_cls  = (const float*)d_in[5];
    const float* b_cls  = (const float*)d_in[6];
    const float* w_box  = (const float*)d_in[7];
    const float* b_box  = (const float*)d_in[8];
    const float* w_fc1  = (const float*)d_in[9];
    const float* b_fc1  = (const float*)d_in[10];
    const float* w_fc2  = (const float*)d_in[11];
    const float* b_fc2  = (const float*)d_in[12];
    const float* w_rcls = (const float*)d_in[13];
    const float* b_rcls = (const float*)d_in[14];
    const float* w_rbox = (const float*)d_in[15];
    const float* b_rbox = (const float*)d_in[16];
    const float* w_m1   = (const float*)d_in[17];
    const float* b_m1   = (const float*)d_in[18];
    const float* w_m2   = (const float*)d_in[19];
    const float* b_m2   = (const float*)d_in[20];
    float* out = (float*)d_out;

    const size_t O_RPNL = 0, O_RPND = 4608, O_PROP = 13824, O_ANCH = 21824;
    const size_t O_RLOG = 31040, O_RDEL = 35040, O_RMSK = 43040;
    const size_t O_FDET = 435040, O_FMSK = 443040, O_FSC = 835040, O_KEEP = 837040;

    float *p_scores, *p_s2, *p_flat, *p_h1, *p_h2, *p_dets, *p_boxes;
    int *p_order, *p_order2, *p_keep1, *p_keep2a;
    unsigned long long *p_mask1, *p_mask2;
    __half *p_bh1, *p_bl1, *p_bh2, *p_bl2;
    cudaGetSymbolAddress((void**)&p_scores, g_scores);
    cudaGetSymbolAddress((void**)&p_order, g_order);
    cudaGetSymbolAddress((void**)&p_s2, g_s2);
    cudaGetSymbolAddress((void**)&p_order2, g_order2);
    cudaGetSymbolAddress((void**)&p_flat, g_flat);
    cudaGetSymbolAddress((void**)&p_h1, g_h1);
    cudaGetSymbolAddress((void**)&p_h2, g_h2);
    cudaGetSymbolAddress((void**)&p_dets, g_dets);
    cudaGetSymbolAddress((void**)&p_boxes, g_boxes);
    cudaGetSymbolAddress((void**)&p_keep1, g_keep1);
    cudaGetSymbolAddress((void**)&p_keep2a, g_keep2a);
    cudaGetSymbolAddress((void**)&p_mask1, g_mask1);
    cudaGetSymbolAddress((void**)&p_mask2, g_mask2);
    cudaGetSymbolAddress((void**)&p_bh1, g_bh1);
    cudaGetSymbolAddress((void**)&p_bl1, g_bl1);
    cudaGetSymbolAddress((void**)&p_bh2, g_bh2);
    cudaGetSymbolAddress((void**)&p_bl2, g_bl2);

    cudaFuncSetAttribute(k_roi, cudaFuncAttributeMaxDynamicSharedMemorySize, SMEM_ROI_BYTES);
    cudaFuncSetAttribute(k_roizero, cudaFuncAttributeMaxDynamicSharedMemorySize, SMEM_ROI_BYTES);

    float4* p_sb1; float* p_sa1; float4* p_sb2; float* p_sa2;
    cudaGetSymbolAddress((void**)&p_sb1, g_sb1);
    cudaGetSymbolAddress((void**)&p_sa1, g_sa1);
    cudaGetSymbolAddress((void**)&p_sb2, g_sb2);
    cudaGetSymbolAddress((void**)&p_sa2, g_sa2);

    k_backbone<<<256, 256>>>(x, w_bb, b_bb);
    k_packwh<<<(9 * 64 * 64 + 255) / 256, 256>>>(w_m1);
    k_packw<<<(64 * 64 * 12 + 255) / 256, 256>>>(w_rpn);
    {
        dim3 tb(32, 8);
        k_packBt<<<dim3(512 / 32, 3136 / 32), tb>>>(w_fc1, p_bh1, p_bl1, 3136, 512);
        k_packBt<<<dim3(512 / 32, 512 / 32), tb>>>(w_fc2, p_bh2, p_bl2, 512, 512);
    }
    k_roizero<<<1, 256, SMEM_ROI_BYTES>>>(b_m1, w_m2, b_m2);
    k_rpnconv<<<256, 512>>>(b_rpn);
    k_heads1<<<18, 128>>>(w_cls, b_cls, w_box, b_box,
                          out + O_RPNL, out + O_RPND, out + O_ANCH);
    k_ranksort<NANCH><<<(NANCH + 255) / 256, 256>>>(p_scores, p_order, p_boxes, p_sb1, p_sa1);
    k_ioumask<NANCH, NW1><<<dim3(NW1, NW1), 64>>>(p_sb1, p_sa1, p_mask1, 0.5f);
    k_nmsreduce<NANCH, NW1><<<1, 32>>>(p_mask1, p_keep1);
    k_select1<<<1, 1024>>>(out + O_PROP);
    k_roi<<<NPROP, 256, SMEM_ROI_BYTES>>>(b_m1, w_m2, b_m2, out + O_RMSK);

    dim3 gfc(8, 32);
    k_gemmh<<<gfc, 256>>>(p_flat, p_bh1, p_bl1, b_fc1, p_h1, NPROP, 512, 3136);
    k_gemmh<<<gfc, 256>>>(p_h1, p_bh2, p_bl2, b_fc2, p_h2, NPROP, 512, 512);
    k_rheads<<<NPROP, 192>>>(w_rcls, b_rcls, w_rbox, b_rbox,
                             out + O_RLOG, out + O_RDEL, p_dets);
    k_ranksort<NPROP><<<(NPROP + 255) / 256, 256>>>(p_s2, p_order2, p_dets, p_sb2, p_sa2);
    k_ioumask<NPROP, NW2><<<dim3(NW2, NW2), 64>>>(p_sb2, p_sa2, p_mask2, 0.3f);
    k_nmsreduce<NPROP, NW2><<<1, 32>>>(p_mask2, p_keep2a);
    float* o_keep = (out_size >= (int)(O_KEEP + NPROP)) ? (out + O_KEEP) : nullptr;
    k_final<<<NPROP, 196>>>(out + O_FDET, out + O_FSC, o_keep, out + O_FMSK);
}